// round 4
// baseline (speedup 1.0000x reference)
#include <cuda_runtime.h>
#include <math.h>
#include <stdint.h>

#define DIMX 512
#define NPOS 49
#define BTOT 2048
#define DHALF 256
#define MROWS 100352    /* BTOT*NPOS */
#define GSTRIDE 25088   /* 512*49 */

/* ------------------- scratch (static, no allocation) ------------------- */
__device__ float g_xz   [(size_t)MROWS * DIMX];   /* fused pre+in_proj out (b,l,512) */
__device__ float g_xconv[(size_t)MROWS * DHALF];  /* silu(conv(x)) (b,l,256)         */
__device__ float g_dt   [(size_t)MROWS * DHALF];  /* dt after dt_proj (b,l,256)      */
__device__ float g_dtin [(size_t)MROWS * 32];     /* LN'd dt-rank part               */
__device__ float g_BC   [(size_t)MROWS * 16];     /* LN'd B(8),C(8) per (b,l)        */
__device__ float g_ycat [(size_t)MROWS * DIMX];   /* [y_scan | z_conv] (b,l,512)     */
__device__ float g_Wc   [4 * DIMX * DIMX];        /* W_in @ W_pre_g                  */
__device__ float g_bc   [4 * DIMX];               /* W_in @ b_pre_g                  */
__device__ float g_Wo   [4 * DIMX * DIMX];        /* W_post_g @ W_out                */
__device__ float g_b2   [DIMX];                   /* sum_g gate_g * b_post_g         */
__device__ float g_gates[4];

/* ------------------- permutation index tables ------------------- */
__constant__ int c_idx[4][49] = {
  { 0,1,2,3,4,5,6,7,8,9,10,11,12,13,14,15,16,17,18,19,20,21,22,23,24,
    25,26,27,28,29,30,31,32,33,34,35,36,37,38,39,40,41,42,43,44,45,46,47,48 },
  { 0,7,14,21,28,35,42, 1,8,15,22,29,36,43, 2,9,16,23,30,37,44,
    3,10,17,24,31,38,45, 4,11,18,25,32,39,46, 5,12,19,26,33,40,47,
    6,13,20,27,34,41,48 },
  { 0, 1,7, 2,8,14, 3,9,15,21, 4,10,16,22,28, 5,11,17,23,29,35,
    6,12,18,24,30,36,42, 13,19,25,31,37,43, 20,26,32,38,44,
    27,33,39,45, 34,40,46, 41,47, 48 },
  { 6, 5,13, 4,12,20, 3,11,19,27, 2,10,18,26,34, 1,9,17,25,33,41,
    0,8,16,24,32,40,48, 7,15,23,31,39,47, 14,22,30,38,46,
    21,29,37,45, 28,36,44, 35,43, 42 }
};

/* ------------------- shared 128x128x8 tile microkernel ------------------- */
__device__ __forceinline__ void tile_fma(const float (&As)[8][128], const float (&Ws)[8][128],
                                         float (&acc)[8][8], int tm, int tn) {
#pragma unroll
  for (int k = 0; k < 8; ++k) {
    float4 a0 = *(const float4*)&As[k][tm];
    float4 a1 = *(const float4*)&As[k][tm + 4];
    float4 w0 = *(const float4*)&Ws[k][tn];
    float4 w1 = *(const float4*)&Ws[k][tn + 4];
    float a[8] = {a0.x,a0.y,a0.z,a0.w,a1.x,a1.y,a1.z,a1.w};
    float w[8] = {w0.x,w0.y,w0.z,w0.w,w1.x,w1.y,w1.z,w1.w};
#pragma unroll
    for (int i = 0; i < 8; ++i)
#pragma unroll
      for (int j = 0; j < 8; ++j)
        acc[i][j] = fmaf(a[i], w[j], acc[i][j]);
  }
}

/* ------------------- weight-folding prep: 8x NN 512^3 GEMMs ------------------- */
struct NNArgs { const float* A[8]; const float* B[8]; };

__global__ void __launch_bounds__(256) gemm_nn_kernel(NNArgs args) {
  __shared__ __align__(16) float As[8][128];
  __shared__ __align__(16) float Bs[8][128];
  int tid = threadIdx.x;
  int z = blockIdx.z;
  const float* __restrict__ A = args.A[z];
  const float* __restrict__ B = args.B[z];
  float* __restrict__ C = (z < 4) ? (g_Wc + (size_t)z * DIMX * DIMX)
                                  : (g_Wo + (size_t)(z - 4) * DIMX * DIMX);
  int m0 = blockIdx.x * 128, n0 = blockIdx.y * 128;
  float acc[8][8];
#pragma unroll
  for (int i = 0; i < 8; ++i)
#pragma unroll
    for (int j = 0; j < 8; ++j) acc[i][j] = 0.f;
  int ar = tid >> 1, ac = (tid & 1) * 4;
  int bk = tid >> 5, bn = (tid & 31) * 4;
  for (int k0 = 0; k0 < DIMX; k0 += 8) {
    float4 av = *(const float4*)(A + (size_t)(m0 + ar) * DIMX + k0 + ac);
    float4 bv = *(const float4*)(B + (size_t)(k0 + bk) * DIMX + n0 + bn);
    As[ac][ar] = av.x; As[ac+1][ar] = av.y; As[ac+2][ar] = av.z; As[ac+3][ar] = av.w;
    *(float4*)&Bs[bk][bn] = bv;
    __syncthreads();
    tile_fma(As, Bs, acc, (tid >> 4) * 8, (tid & 15) * 8);
    __syncthreads();
  }
  int tm = (tid >> 4) * 8, tn = (tid & 15) * 8;
#pragma unroll
  for (int i = 0; i < 8; ++i) {
    float* o = C + (size_t)(m0 + tm + i) * DIMX + n0 + tn;
    float4 v0 = {acc[i][0], acc[i][1], acc[i][2], acc[i][3]};
    float4 v1 = {acc[i][4], acc[i][5], acc[i][6], acc[i][7]};
    *(float4*)o = v0; *(float4*)(o + 4) = v1;
  }
}

__global__ void bias1_kernel(const float* __restrict__ inW,
                             const float* b0, const float* b1,
                             const float* b2, const float* b3) {
  int g = blockIdx.x, o = threadIdx.x;
  const float* pb = (g == 0) ? b0 : (g == 1) ? b1 : (g == 2) ? b2 : b3;
  const float* wr = inW + (size_t)o * DIMX;
  float s = 0.f;
  for (int k = 0; k < DIMX; ++k) s = fmaf(wr[k], pb[k], s);
  g_bc[g * DIMX + o] = s;
}

__global__ void gates_bias2_kernel(const float* __restrict__ gl,
                                   const float* b0, const float* b1,
                                   const float* b2, const float* b3) {
  __shared__ float sg[4];
  int t = threadIdx.x;
  if (t == 0) {
    float a0 = gl[0], a1 = gl[1], a2 = gl[2], a3 = gl[3];
    float m = fmaxf(fmaxf(a0, a1), fmaxf(a2, a3));
    float e0 = __expf(a0 - m), e1 = __expf(a1 - m), e2 = __expf(a2 - m), e3 = __expf(a3 - m);
    float inv = 1.f / (e0 + e1 + e2 + e3);
    sg[0] = e0 * inv; sg[1] = e1 * inv; sg[2] = e2 * inv; sg[3] = e3 * inv;
    g_gates[0] = sg[0]; g_gates[1] = sg[1]; g_gates[2] = sg[2]; g_gates[3] = sg[3];
  }
  __syncthreads();
  g_b2[t] = sg[0]*b0[t] + sg[1]*b1[t] + sg[2]*b2[t] + sg[3]*b3[t];
}

/* ---------- GEMM1: gathered tokens @ Wc_g^T + bc_g -> g_xz ---------- */
__global__ void __launch_bounds__(256) gemm1_kernel(const float* __restrict__ tokens) {
  __shared__ __align__(16) float As[8][128];
  __shared__ __align__(16) float Ws[8][128];
  __shared__ const float* rowp[128];
  int tid = threadIdx.x;
  int bm = blockIdx.x, bn = blockIdx.y;
  int g = bm / 196;
  int m0 = bm * 128, n0 = bn * 128;
  const float* __restrict__ W = g_Wc + (size_t)g * DIMX * DIMX;
  if (tid < 128) {
    int m = m0 + tid - g * GSTRIDE;
    int b = m / 49, i = m - b * 49;
    rowp[tid] = tokens + ((size_t)b * 49 + c_idx[g][i]) * DIMX;
  }
  __syncthreads();
  float acc[8][8];
#pragma unroll
  for (int i = 0; i < 8; ++i)
#pragma unroll
    for (int j = 0; j < 8; ++j) acc[i][j] = 0.f;
  int ar = tid >> 1, ac = (tid & 1) * 4;
  const float* wrow = W + (size_t)(n0 + ar) * DIMX + ac;
  for (int k0 = 0; k0 < DIMX; k0 += 8) {
    float4 av = *(const float4*)(rowp[ar] + k0 + ac);
    float4 wv = *(const float4*)(wrow + k0);
    As[ac][ar] = av.x; As[ac+1][ar] = av.y; As[ac+2][ar] = av.z; As[ac+3][ar] = av.w;
    Ws[ac][ar] = wv.x; Ws[ac+1][ar] = wv.y; Ws[ac+2][ar] = wv.z; Ws[ac+3][ar] = wv.w;
    __syncthreads();
    tile_fma(As, Ws, acc, (tid >> 4) * 8, (tid & 15) * 8);
    __syncthreads();
  }
  int tm = (tid >> 4) * 8, tn = (tid & 15) * 8;
  const float* bias = g_bc + g * DIMX + n0 + tn;
  float bv[8];
#pragma unroll
  for (int j = 0; j < 8; ++j) bv[j] = bias[j];
#pragma unroll
  for (int i = 0; i < 8; ++i) {
    float* o = g_xz + (size_t)(m0 + tm + i) * DIMX + n0 + tn;
    float4 v0 = {acc[i][0]+bv[0], acc[i][1]+bv[1], acc[i][2]+bv[2], acc[i][3]+bv[3]};
    float4 v1 = {acc[i][4]+bv[4], acc[i][5]+bv[5], acc[i][6]+bv[6], acc[i][7]+bv[7]};
    *(float4*)o = v0; *(float4*)(o + 4) = v1;
  }
}

/* ---------- depthwise conv(k=3, SAME) + silu ---------- */
__global__ void __launch_bounds__(256) conv_kernel(const float* __restrict__ cxw,
                                                   const float* __restrict__ cxb,
                                                   const float* __restrict__ czw,
                                                   const float* __restrict__ czb) {
  int row = blockIdx.x;            /* (b*49 + l) */
  int d = threadIdx.x;             /* 0..255 */
  int l = row % 49;
  const float* base = g_xz + (size_t)row * DIMX;
  float xm = (l > 0)  ? base[-DIMX + d] : 0.f;
  float x0 = base[d];
  float xp = (l < 48) ? base[ DIMX + d] : 0.f;
  float v = fmaf(cxw[d*3], xm, fmaf(cxw[d*3+1], x0, fmaf(cxw[d*3+2], xp, cxb[d])));
  v = v / (1.f + __expf(-v));
  g_xconv[(size_t)row * DHALF + d] = v;
  float zm = (l > 0)  ? base[-DIMX + DHALF + d] : 0.f;
  float z0 = base[DHALF + d];
  float zp = (l < 48) ? base[ DIMX + DHALF + d] : 0.f;
  float vz = fmaf(czw[d*3], zm, fmaf(czw[d*3+1], z0, fmaf(czw[d*3+2], zp, czb[d])));
  vz = vz / (1.f + __expf(-vz));
  g_ycat[(size_t)row * DIMX + DHALF + d] = vz;
}

/* ---------- x_proj (256->48) + layernorm(48), 8 rows/block ---------- */
__global__ void __launch_bounds__(256) xdbl_kernel(const float* __restrict__ xpw,
                                                   const float* __restrict__ lnw,
                                                   const float* __restrict__ lnb) {
  extern __shared__ float sm[];
  float* xw = sm;                 /* 48 x 257 */
  float* xr = sm + 48 * 257;      /* 8 x 257  */
  float* xd = xr + 8 * 257;       /* 8 x 48   */
  int tid = threadIdx.x;
  int row0 = blockIdx.x * 8;
  for (int i = tid; i < 48 * 256; i += 256) xw[(i >> 8) * 257 + (i & 255)] = xpw[i];
  const float* src = g_xconv + (size_t)row0 * DHALF;
  for (int i = tid; i < 8 * 256; i += 256) xr[(i >> 8) * 257 + (i & 255)] = src[i];
  __syncthreads();
  for (int o = tid; o < 384; o += 256) {
    int r = o / 48, e = o - r * 48;
    const float* xp = xr + r * 257;
    const float* wp = xw + e * 257;
    float s = 0.f;
#pragma unroll 8
    for (int k = 0; k < 256; ++k) s = fmaf(xp[k], wp[k], s);
    xd[r * 48 + e] = s;
  }
  __syncthreads();
  int w = tid >> 5, lane = tid & 31;
  float v0 = xd[w * 48 + lane];
  float v1 = (lane < 16) ? xd[w * 48 + 32 + lane] : 0.f;
  float s = v0 + v1, sq = v0 * v0 + v1 * v1;
#pragma unroll
  for (int off = 16; off > 0; off >>= 1) {
    s  += __shfl_xor_sync(0xffffffffu, s, off);
    sq += __shfl_xor_sync(0xffffffffu, sq, off);
  }
  float mean = s * (1.f / 48.f);
  float var = sq * (1.f / 48.f) - mean * mean;
  float rstd = rsqrtf(var + 1e-5f);
  int grow = row0 + w;
  {
    int e = lane;  /* 0..31 -> dt_in */
    float y = (v0 - mean) * rstd * lnw[e] + lnb[e];
    g_dtin[(size_t)grow * 32 + e] = y;
  }
  if (lane < 16) {
    int e = 32 + lane;  /* 32..47 -> B,C */
    float y = (v1 - mean) * rstd * lnw[e] + lnb[e];
    g_BC[(size_t)grow * 16 + (e - 32)] = y;
  }
}

/* ---------- dt_proj GEMM: (M x 32) @ (256 x 32)^T -> g_dt ---------- */
__global__ void __launch_bounds__(256) gemm_dt_kernel(const float* __restrict__ dtw) {
  __shared__ __align__(16) float As[8][128];
  __shared__ __align__(16) float Ws[8][128];
  int tid = threadIdx.x;
  int m0 = blockIdx.x * 128, n0 = blockIdx.y * 128;
  float acc[8][8];
#pragma unroll
  for (int i = 0; i < 8; ++i)
#pragma unroll
    for (int j = 0; j < 8; ++j) acc[i][j] = 0.f;
  int ar = tid >> 1, ac = (tid & 1) * 4;
  const float* arow = g_dtin + (size_t)(m0 + ar) * 32 + ac;
  const float* wrow = dtw + (size_t)(n0 + ar) * 32 + ac;
  for (int k0 = 0; k0 < 32; k0 += 8) {
    float4 av = *(const float4*)(arow + k0);
    float4 wv = *(const float4*)(wrow + k0);
    As[ac][ar] = av.x; As[ac+1][ar] = av.y; As[ac+2][ar] = av.z; As[ac+3][ar] = av.w;
    Ws[ac][ar] = wv.x; Ws[ac+1][ar] = wv.y; Ws[ac+2][ar] = wv.z; Ws[ac+3][ar] = wv.w;
    __syncthreads();
    tile_fma(As, Ws, acc, (tid >> 4) * 8, (tid & 15) * 8);
    __syncthreads();
  }
  int tm = (tid >> 4) * 8, tn = (tid & 15) * 8;
#pragma unroll
  for (int i = 0; i < 8; ++i) {
    float* o = g_dt + (size_t)(m0 + tm + i) * DHALF + n0 + tn;
    float4 v0 = {acc[i][0], acc[i][1], acc[i][2], acc[i][3]};
    float4 v1 = {acc[i][4], acc[i][5], acc[i][6], acc[i][7]};
    *(float4*)o = v0; *(float4*)(o + 4) = v1;
  }
}

/* ---------- selective scan: block per batch, thread per channel ---------- */
__global__ void __launch_bounds__(256) scan_kernel(const float* __restrict__ A_log,
                                                   const float* __restrict__ dtb_v,
                                                   const float* __restrict__ Dp) {
  __shared__ float bc[49 * 16];
  int b = blockIdx.x, d = threadIdx.x;
  for (int i = d; i < 49 * 16; i += 256) bc[i] = g_BC[(size_t)b * 49 * 16 + i];
  __syncthreads();
  float Ar[8];
#pragma unroll
  for (int n = 0; n < 8; ++n) Ar[n] = -expf(A_log[d * 8 + n]);
  float dtb = dtb_v[d], Dv = Dp[d];
  float h[8];
#pragma unroll
  for (int n = 0; n < 8; ++n) h[n] = 0.f;
  const float* dtp = g_dt + (size_t)b * 49 * DHALF + d;
  const float* up  = g_xconv + (size_t)b * 49 * DHALF + d;
  float* yp = g_ycat + (size_t)b * 49 * DIMX + d;
  for (int l = 0; l < 49; ++l) {
    float dtv = dtp[l * DHALF] + dtb;
    dtv = (dtv > 20.f) ? dtv : log1pf(__expf(dtv));
    float u = up[l * DHALF];
    float dbu = dtv * u;
    const float* B = &bc[l * 16];
    float y = 0.f;
#pragma unroll
    for (int n = 0; n < 8; ++n) {
      h[n] = fmaf(h[n], __expf(dtv * Ar[n]), dbu * B[n]);
      y = fmaf(h[n], B[8 + n], y);
    }
    y = fmaf(Dv, u, y);
    if (!isfinite(y)) y = isnan(y) ? 0.f : copysignf(3.402823466e38f, y);
    yp[l * DIMX] = y;
  }
}

/* ---------- GEMM2: out = sum_g gate_g * ycat_g @ Wo_g^T + b2 ---------- */
__global__ void __launch_bounds__(256) gemm2_kernel(float* __restrict__ out) {
  __shared__ __align__(16) float As[8][128];
  __shared__ __align__(16) float Ws[8][128];
  int tid = threadIdx.x;
  int m0 = blockIdx.x * 128, n0 = blockIdx.y * 128;
  float acc[8][8];
#pragma unroll
  for (int i = 0; i < 8; ++i)
#pragma unroll
    for (int j = 0; j < 8; ++j) acc[i][j] = 0.f;
  int ar = tid >> 1, ac = (tid & 1) * 4;
  for (int g = 0; g < 4; ++g) {
    float gate = g_gates[g];
    const float* arow = g_ycat + (size_t)(g * GSTRIDE + m0 + ar) * DIMX + ac;
    const float* wrow = g_Wo + (size_t)g * DIMX * DIMX + (size_t)(n0 + ar) * DIMX + ac;
    for (int k0 = 0; k0 < DIMX; k0 += 8) {
      float4 av = *(const float4*)(arow + k0);
      float4 wv = *(const float4*)(wrow + k0);
      av.x *= gate; av.y *= gate; av.z *= gate; av.w *= gate;
      As[ac][ar] = av.x; As[ac+1][ar] = av.y; As[ac+2][ar] = av.z; As[ac+3][ar] = av.w;
      Ws[ac][ar] = wv.x; Ws[ac+1][ar] = wv.y; Ws[ac+2][ar] = wv.z; Ws[ac+3][ar] = wv.w;
      __syncthreads();
      tile_fma(As, Ws, acc, (tid >> 4) * 8, (tid & 15) * 8);
      __syncthreads();
    }
  }
  int tm = (tid >> 4) * 8, tn = (tid & 15) * 8;
  float bv[8];
#pragma unroll
  for (int j = 0; j < 8; ++j) bv[j] = g_b2[n0 + tn + j];
#pragma unroll
  for (int i = 0; i < 8; ++i) {
    float* o = out + (size_t)(m0 + tm + i) * DIMX + n0 + tn;
    float4 v0 = {acc[i][0]+bv[0], acc[i][1]+bv[1], acc[i][2]+bv[2], acc[i][3]+bv[3]};
    float4 v1 = {acc[i][4]+bv[4], acc[i][5]+bv[5], acc[i][6]+bv[6], acc[i][7]+bv[7]};
    *(float4*)o = v0; *(float4*)(o + 4) = v1;
  }
}

/* ------------------- launch ------------------- */
extern "C" void kernel_launch(void* const* d_in, const int* in_sizes, int n_in,
                              void* d_out, int out_size) {
  const float *tokens, *pre_w[4], *pre_b[4], *post_w[4], *post_b[4];
  const float *in_proj_w, *conv_x_w, *conv_x_b, *conv_z_w, *conv_z_b;
  const float *x_proj_w, *ln_w, *ln_b, *dt_proj_w, *dt_proj_b;
  const float *A_log, *D_param, *out_proj_w, *gate_logits;

  tokens = (const float*)d_in[0];
  for (int g = 0; g < 4; ++g) {
    pre_w[g] = (const float*)d_in[1 + 2 * g];
    pre_b[g] = (const float*)d_in[2 + 2 * g];
  }
  if (in_sizes[10] == 768) {
    /* reference-signature order: ..., pre_a_b, in_proj_w, conv..., out_proj_w, post_*, gate */
    in_proj_w = (const float*)d_in[9];
    conv_x_w = (const float*)d_in[10]; conv_x_b = (const float*)d_in[11];
    conv_z_w = (const float*)d_in[12]; conv_z_b = (const float*)d_in[13];
    x_proj_w = (const float*)d_in[14];
    ln_w = (const float*)d_in[15]; ln_b = (const float*)d_in[16];
    dt_proj_w = (const float*)d_in[17]; dt_proj_b = (const float*)d_in[18];
    A_log = (const float*)d_in[19]; D_param = (const float*)d_in[20];
    out_proj_w = (const float*)d_in[21];
    for (int g = 0; g < 4; ++g) {
      post_w[g] = (const float*)d_in[22 + 2 * g];
      post_b[g] = (const float*)d_in[23 + 2 * g];
    }
    gate_logits = (const float*)d_in[30];
  } else {
    /* setup_inputs dict order: ..., pre_a_b, post_h_w..post_a_b, in_proj_w, conv..., gate */
    for (int g = 0; g < 4; ++g) {
      post_w[g] = (const float*)d_in[9 + 2 * g];
      post_b[g] = (const float*)d_in[10 + 2 * g];
    }
    in_proj_w = (const float*)d_in[17];
    conv_x_w = (const float*)d_in[18]; conv_x_b = (const float*)d_in[19];
    conv_z_w = (const float*)d_in[20]; conv_z_b = (const float*)d_in[21];
    x_proj_w = (const float*)d_in[22];
    ln_w = (const float*)d_in[23]; ln_b = (const float*)d_in[24];
    dt_proj_w = (const float*)d_in[25]; dt_proj_b = (const float*)d_in[26];
    A_log = (const float*)d_in[27]; D_param = (const float*)d_in[28];
    out_proj_w = (const float*)d_in[29];
    gate_logits = (const float*)d_in[30];
  }
  float* out = (float*)d_out;

  cudaFuncSetAttribute(xdbl_kernel, cudaFuncAttributeMaxDynamicSharedMemorySize, 60416);

  /* 1. fold weights: Wc_g = W_in @ W_pre_g ; Wo_g = W_post_g @ W_out */
  NNArgs na;
  for (int g = 0; g < 4; ++g) {
    na.A[g] = in_proj_w;  na.B[g] = pre_w[g];
    na.A[4+g] = post_w[g]; na.B[4+g] = out_proj_w;
  }
  gemm_nn_kernel<<<dim3(4, 4, 8), 256>>>(na);
  bias1_kernel<<<4, 512>>>(in_proj_w, pre_b[0], pre_b[1], pre_b[2], pre_b[3]);
  gates_bias2_kernel<<<1, 512>>>(gate_logits, post_b[0], post_b[1], post_b[2], post_b[3]);

  /* 2. fused pre-proj(+perm) + in_proj */
  gemm1_kernel<<<dim3(784, 4), 256>>>(tokens);

  /* 3. depthwise conv + silu (z half lands directly in ycat) */
  conv_kernel<<<MROWS, 256>>>(conv_x_w, conv_x_b, conv_z_w, conv_z_b);

  /* 4. x_proj + layernorm */
  xdbl_kernel<<<MROWS / 8, 256, 60416>>>(x_proj_w, ln_w, ln_b);

  /* 5. dt_proj */
  gemm_dt_kernel<<<dim3(784, 2), 256>>>(dt_proj_w);

  /* 6. selective scan */
  scan_kernel<<<BTOT, 256>>>(A_log, dt_proj_b, D_param);

  /* 7. fused out_proj + gated post-projections */
  gemm2_kernel<<<dim3(196, 4), 256>>>(out);
}

// round 10
// speedup vs baseline: 1.8821x; 1.8821x over previous
#include <cuda_runtime.h>
#include <cuda_bf16.h>
#include <math.h>
#include <stdint.h>

#define DIMX 512
#define NPOS 49
#define BTOT 2048
#define DHALF 256
#define MROWS 100352    /* BTOT*NPOS */
#define GSTRIDE 25088   /* 512*49 */

/* ------------------- scratch (static, no allocation) ------------------- */
__device__ float g_xz   [(size_t)MROWS * DIMX];
__device__ float g_xconv[(size_t)MROWS * DHALF];
__device__ float g_dt   [(size_t)MROWS * DHALF];
__device__ float g_dtin [(size_t)MROWS * 32];
__device__ float g_BC   [(size_t)MROWS * 16];
__device__ float g_ycat [(size_t)MROWS * DIMX];
__device__ float g_Wc   [4 * DIMX * DIMX];
__device__ float g_bc   [4 * DIMX];
__device__ float g_Wo   [4 * DIMX * DIMX];
__device__ float g_b2   [DIMX];
__device__ float g_gates[4];
__device__ __nv_bfloat16 g_Wc_h[4 * DIMX * DIMX];
__device__ __nv_bfloat16 g_Wc_l[4 * DIMX * DIMX];
__device__ __nv_bfloat16 g_Wo_h[4 * DIMX * DIMX];
__device__ __nv_bfloat16 g_Wo_l[4 * DIMX * DIMX];

/* ------------------- permutation index tables ------------------- */
__constant__ int c_idx[4][49] = {
  { 0,1,2,3,4,5,6,7,8,9,10,11,12,13,14,15,16,17,18,19,20,21,22,23,24,
    25,26,27,28,29,30,31,32,33,34,35,36,37,38,39,40,41,42,43,44,45,46,47,48 },
  { 0,7,14,21,28,35,42, 1,8,15,22,29,36,43, 2,9,16,23,30,37,44,
    3,10,17,24,31,38,45, 4,11,18,25,32,39,46, 5,12,19,26,33,40,47,
    6,13,20,27,34,41,48 },
  { 0, 1,7, 2,8,14, 3,9,15,21, 4,10,16,22,28, 5,11,17,23,29,35,
    6,12,18,24,30,36,42, 13,19,25,31,37,43, 20,26,32,38,44,
    27,33,39,45, 34,40,46, 41,47, 48 },
  { 6, 5,13, 4,12,20, 3,11,19,27, 2,10,18,26,34, 1,9,17,25,33,41,
    0,8,16,24,32,40,48, 7,15,23,31,39,47, 14,22,30,38,46,
    21,29,37,45, 28,36,44, 35,43, 42 }
};

/* ======================= mma.sync helpers ======================= */
__device__ __forceinline__ uint32_t smem_u32(const void* p) {
  uint32_t a;
  asm("{ .reg .u64 t; cvta.to.shared.u64 t, %1; cvt.u32.u64 %0, t; }" : "=r"(a) : "l"(p));
  return a;
}
__device__ __forceinline__ void ldsm4(uint32_t* r, uint32_t addr) {
  asm volatile("ldmatrix.sync.aligned.m8n8.x4.shared.b16 {%0,%1,%2,%3}, [%4];"
               : "=r"(r[0]), "=r"(r[1]), "=r"(r[2]), "=r"(r[3]) : "r"(addr));
}
__device__ __forceinline__ void mma16816(float* c, const uint32_t* a, const uint32_t* b) {
  asm volatile("mma.sync.aligned.m16n8k16.row.col.f32.bf16.bf16.f32 "
               "{%0,%1,%2,%3}, {%4,%5,%6,%7}, {%8,%9}, {%0,%1,%2,%3};"
               : "+f"(c[0]), "+f"(c[1]), "+f"(c[2]), "+f"(c[3])
               : "r"(a[0]), "r"(a[1]), "r"(a[2]), "r"(a[3]), "r"(b[0]), "r"(b[1]));
}

/* split float4 into bf16-hi and bf16-lo packed pairs */
__device__ __forceinline__ void split4(float4 v, uint2& hi, uint2& lo) {
  __nv_bfloat162 h0 = __floats2bfloat162_rn(v.x, v.y);
  __nv_bfloat162 h1 = __floats2bfloat162_rn(v.z, v.w);
  float rx = v.x - __bfloat162float(h0.x);
  float ry = v.y - __bfloat162float(h0.y);
  float rz = v.z - __bfloat162float(h1.x);
  float rw = v.w - __bfloat162float(h1.y);
  __nv_bfloat162 l0 = __floats2bfloat162_rn(rx, ry);
  __nv_bfloat162 l1 = __floats2bfloat162_rn(rz, rw);
  hi.x = *(uint32_t*)&h0; hi.y = *(uint32_t*)&h1;
  lo.x = *(uint32_t*)&l0; lo.y = *(uint32_t*)&l1;
}

/* smem layout (bf16, LDA = 72 elements = 144B rows, conflict-free ldmatrix) */
#define LDA      72
#define OFF_AH   0
#define OFF_AL   18432
#define OFF_BH   36864
#define OFF_BL   55296
#define OFF_ROWP 73728
#define SMEM_MM  74752

/* =================== HMMA split-bf16 GEMM (G2=0: gemm1, G2=1: gemm2) =================== */
template<int G2>
__global__ void __launch_bounds__(256) gemm_mma(const float* __restrict__ src,
                                                float* __restrict__ dstp) {
  extern __shared__ __align__(16) char sm[];
  const int NCH = G2 ? 32 : 8;
  int tid = threadIdx.x, wid = tid >> 5, lane = tid & 31;
  int warp_m = wid & 3, warp_n = wid >> 1 & ~0;  /* fixed below */
  warp_n = wid >> 2;
  int bm = blockIdx.x, bn = blockIdx.y;
  int m0 = bm * 128, n0 = bn * 128;
  uint32_t smb = smem_u32(sm);

  const float** rowp = (const float**)(sm + OFF_ROWP);
  int g1 = 0;
  if (!G2) {
    g1 = bm / 196;
    if (tid < 128) {
      int m = m0 + tid - g1 * GSTRIDE;
      int b = m / 49, i = m - b * 49;
      rowp[tid] = src + ((size_t)b * 49 + c_idx[g1][i]) * DIMX;
    }
    __syncthreads();
  }

  float acc[2][8][4];
#pragma unroll
  for (int t = 0; t < 2; ++t)
#pragma unroll
    for (int n = 0; n < 8; ++n)
#pragma unroll
      for (int e = 0; e < 4; ++e) acc[t][n][e] = 0.f;

  /* ldmatrix source addresses (fixed per thread, offset by k each step) */
  uint32_t a_row = warp_m * 32 + (lane & 15);
  uint32_t a_coff = (lane >> 4) << 3;
  uint32_t b_row = warp_n * 64 + ((lane >> 4) << 3) + (lane & 7);
  uint32_t b_coff = ((lane >> 3) & 1) << 3;

  for (int c = 0; c < NCH; ++c) {
    int gq = G2 ? (c >> 3) : g1;
    int k0 = (G2 ? (c & 7) : c) * 64;
    const __nv_bfloat16* Wh = (G2 ? g_Wo_h : g_Wc_h) + (size_t)gq * DIMX * DIMX;
    const __nv_bfloat16* Wl = (G2 ? g_Wo_l : g_Wc_l) + (size_t)gq * DIMX * DIMX;
    float gate = G2 ? g_gates[gq] : 1.f;

    __syncthreads();   /* previous chunk's mma reads done */

    /* ---- fill A: 128 rows x 64 k fp32 -> hi/lo bf16 planes ---- */
#pragma unroll
    for (int i = 0; i < 8; ++i) {
      int slot = tid + i * 256;
      int r = slot >> 4, c4 = slot & 15;
      const float* ap = G2 ? (g_ycat + (size_t)(gq * GSTRIDE + m0 + r) * DIMX + k0 + c4 * 4)
                           : (rowp[r] + k0 + c4 * 4);
      float4 v = *(const float4*)ap;
      if (G2) { v.x *= gate; v.y *= gate; v.z *= gate; v.w *= gate; }
      uint2 hi, lo;
      split4(v, hi, lo);
      int off = (r * LDA + c4 * 4) * 2;
      *(uint2*)(sm + OFF_AH + off) = hi;
      *(uint2*)(sm + OFF_AL + off) = lo;
    }
    /* ---- fill B: 128 n-rows x 64 k, pre-split bf16 planes ---- */
#pragma unroll
    for (int i = 0; i < 8; ++i) {
      int slot = tid + i * 256;
      int plane = slot >> 10, idx = slot & 1023;
      int r = idx >> 3, u = idx & 7;
      const __nv_bfloat16* bp = (plane ? Wl : Wh) + (size_t)(n0 + r) * DIMX + k0 + u * 8;
      uint4 v = *(const uint4*)bp;
      *(uint4*)(sm + (plane ? OFF_BL : OFF_BH) + (r * LDA + u * 8) * 2) = v;
    }
    __syncthreads();

    /* ---- mma over 4 k16 steps ---- */
#pragma unroll
    for (int kk = 0; kk < 4; ++kk) {
      int k = kk * 16;
      uint32_t ah[2][4], al[2][4], bh[8][2], bl[8][2];
#pragma unroll
      for (int t = 0; t < 2; ++t) {
        uint32_t off = ((a_row + t * 16) * LDA + k + a_coff) * 2;
        ldsm4(ah[t], smb + OFF_AH + off);
        ldsm4(al[t], smb + OFF_AL + off);
      }
#pragma unroll
      for (int p = 0; p < 4; ++p) {
        uint32_t off = ((b_row + p * 16) * LDA + k + b_coff) * 2;
        uint32_t rh[4], rl[4];
        ldsm4(rh, smb + OFF_BH + off);
        ldsm4(rl, smb + OFF_BL + off);
        bh[2*p][0] = rh[0]; bh[2*p][1] = rh[1]; bh[2*p+1][0] = rh[2]; bh[2*p+1][1] = rh[3];
        bl[2*p][0] = rl[0]; bl[2*p][1] = rl[1]; bl[2*p+1][0] = rl[2]; bl[2*p+1][1] = rl[3];
      }
#pragma unroll
      for (int t = 0; t < 2; ++t)
#pragma unroll
        for (int n = 0; n < 8; ++n) {
          mma16816(acc[t][n], ah[t], bh[n]);
          mma16816(acc[t][n], al[t], bh[n]);
          mma16816(acc[t][n], ah[t], bl[n]);
        }
    }
  }

  /* ---- epilogue: direct STG + bias ---- */
  const float* bias = (G2 ? g_b2 : g_bc + g1 * DIMX) + n0;
  float* dst = G2 ? dstp : g_xz;
#pragma unroll
  for (int t = 0; t < 2; ++t) {
    int mrow = m0 + warp_m * 32 + t * 16 + (lane >> 2);
#pragma unroll
    for (int n = 0; n < 8; ++n) {
      int cl = warp_n * 64 + n * 8 + (lane & 3) * 2;
      float b0 = bias[cl], b1 = bias[cl + 1];
      float2 v0 = {acc[t][n][0] + b0, acc[t][n][1] + b1};
      float2 v1 = {acc[t][n][2] + b0, acc[t][n][3] + b1};
      *(float2*)(dst + (size_t)mrow * DIMX + n0 + cl) = v0;
      *(float2*)(dst + (size_t)(mrow + 8) * DIMX + n0 + cl) = v1;
    }
  }
}

/* ------------------- fp32 128x128x8 tile microkernel (prep) ------------------- */
__device__ __forceinline__ void tile_fma(const float (&As)[8][128], const float (&Ws)[8][128],
                                         float (&acc)[8][8], int tm, int tn) {
#pragma unroll
  for (int k = 0; k < 8; ++k) {
    float4 a0 = *(const float4*)&As[k][tm];
    float4 a1 = *(const float4*)&As[k][tm + 4];
    float4 w0 = *(const float4*)&Ws[k][tn];
    float4 w1 = *(const float4*)&Ws[k][tn + 4];
    float a[8] = {a0.x,a0.y,a0.z,a0.w,a1.x,a1.y,a1.z,a1.w};
    float w[8] = {w0.x,w0.y,w0.z,w0.w,w1.x,w1.y,w1.z,w1.w};
#pragma unroll
    for (int i = 0; i < 8; ++i)
#pragma unroll
      for (int j = 0; j < 8; ++j)
        acc[i][j] = fmaf(a[i], w[j], acc[i][j]);
  }
}

struct NNArgs { const float* A[8]; const float* B[8]; };

__global__ void __launch_bounds__(256) gemm_nn_kernel(NNArgs args) {
  __shared__ __align__(16) float As[8][128];
  __shared__ __align__(16) float Bs[8][128];
  int tid = threadIdx.x;
  int z = blockIdx.z;
  const float* __restrict__ A = args.A[z];
  const float* __restrict__ B = args.B[z];
  float* __restrict__ C = (z < 4) ? (g_Wc + (size_t)z * DIMX * DIMX)
                                  : (g_Wo + (size_t)(z - 4) * DIMX * DIMX);
  int m0 = blockIdx.x * 128, n0 = blockIdx.y * 128;
  float acc[8][8];
#pragma unroll
  for (int i = 0; i < 8; ++i)
#pragma unroll
    for (int j = 0; j < 8; ++j) acc[i][j] = 0.f;
  int ar = tid >> 1, ac = (tid & 1) * 4;
  int bk = tid >> 5, bn = (tid & 31) * 4;
  for (int k0 = 0; k0 < DIMX; k0 += 8) {
    float4 av = *(const float4*)(A + (size_t)(m0 + ar) * DIMX + k0 + ac);
    float4 bv = *(const float4*)(B + (size_t)(k0 + bk) * DIMX + n0 + bn);
    As[ac][ar] = av.x; As[ac+1][ar] = av.y; As[ac+2][ar] = av.z; As[ac+3][ar] = av.w;
    *(float4*)&Bs[bk][bn] = bv;
    __syncthreads();
    tile_fma(As, Bs, acc, (tid >> 4) * 8, (tid & 15) * 8);
    __syncthreads();
  }
  int tm = (tid >> 4) * 8, tn = (tid & 15) * 8;
#pragma unroll
  for (int i = 0; i < 8; ++i) {
    float* o = C + (size_t)(m0 + tm + i) * DIMX + n0 + tn;
    float4 v0 = {acc[i][0], acc[i][1], acc[i][2], acc[i][3]};
    float4 v1 = {acc[i][4], acc[i][5], acc[i][6], acc[i][7]};
    *(float4*)o = v0; *(float4*)(o + 4) = v1;
  }
}

/* split folded weights into bf16 hi/lo planes */
__global__ void split_w_kernel() {
  size_t i = (size_t)blockIdx.x * blockDim.x + threadIdx.x;
  float w = g_Wc[i];
  __nv_bfloat16 h = __float2bfloat16(w);
  g_Wc_h[i] = h;
  g_Wc_l[i] = __float2bfloat16(w - __bfloat162float(h));
  float w2 = g_Wo[i];
  __nv_bfloat16 h2 = __float2bfloat16(w2);
  g_Wo_h[i] = h2;
  g_Wo_l[i] = __float2bfloat16(w2 - __bfloat162float(h2));
}

__global__ void bias1_kernel(const float* __restrict__ inW,
                             const float* b0, const float* b1,
                             const float* b2, const float* b3) {
  int g = blockIdx.x, o = threadIdx.x;
  const float* pb = (g == 0) ? b0 : (g == 1) ? b1 : (g == 2) ? b2 : b3;
  const float* wr = inW + (size_t)o * DIMX;
  float s = 0.f;
  for (int k = 0; k < DIMX; ++k) s = fmaf(wr[k], pb[k], s);
  g_bc[g * DIMX + o] = s;
}

__global__ void gates_bias2_kernel(const float* __restrict__ gl,
                                   const float* b0, const float* b1,
                                   const float* b2, const float* b3) {
  __shared__ float sg[4];
  int t = threadIdx.x;
  if (t == 0) {
    float a0 = gl[0], a1 = gl[1], a2 = gl[2], a3 = gl[3];
    float m = fmaxf(fmaxf(a0, a1), fmaxf(a2, a3));
    float e0 = __expf(a0 - m), e1 = __expf(a1 - m), e2 = __expf(a2 - m), e3 = __expf(a3 - m);
    float inv = 1.f / (e0 + e1 + e2 + e3);
    sg[0] = e0 * inv; sg[1] = e1 * inv; sg[2] = e2 * inv; sg[3] = e3 * inv;
    g_gates[0] = sg[0]; g_gates[1] = sg[1]; g_gates[2] = sg[2]; g_gates[3] = sg[3];
  }
  __syncthreads();
  g_b2[t] = sg[0]*b0[t] + sg[1]*b1[t] + sg[2]*b2[t] + sg[3]*b3[t];
}

/* ---------- depthwise conv(k=3, SAME) + silu ---------- */
__global__ void __launch_bounds__(256) conv_kernel(const float* __restrict__ cxw,
                                                   const float* __restrict__ cxb,
                                                   const float* __restrict__ czw,
                                                   const float* __restrict__ czb) {
  int row = blockIdx.x;
  int d = threadIdx.x;
  int l = row % 49;
  const float* base = g_xz + (size_t)row * DIMX;
  float xm = (l > 0)  ? base[-DIMX + d] : 0.f;
  float x0 = base[d];
  float xp = (l < 48) ? base[ DIMX + d] : 0.f;
  float v = fmaf(cxw[d*3], xm, fmaf(cxw[d*3+1], x0, fmaf(cxw[d*3+2], xp, cxb[d])));
  v = v / (1.f + __expf(-v));
  g_xconv[(size_t)row * DHALF + d] = v;
  float zm = (l > 0)  ? base[-DIMX + DHALF + d] : 0.f;
  float z0 = base[DHALF + d];
  float zp = (l < 48) ? base[ DIMX + DHALF + d] : 0.f;
  float vz = fmaf(czw[d*3], zm, fmaf(czw[d*3+1], z0, fmaf(czw[d*3+2], zp, czb[d])));
  vz = vz / (1.f + __expf(-vz));
  g_ycat[(size_t)row * DIMX + DHALF + d] = vz;
}

/* ---------- x_proj (256->48) + layernorm(48), 8 rows/block ---------- */
__global__ void __launch_bounds__(256) xdbl_kernel(const float* __restrict__ xpw,
                                                   const float* __restrict__ lnw,
                                                   const float* __restrict__ lnb) {
  extern __shared__ float smf[];
  float* xw = smf;
  float* xr = smf + 48 * 257;
  float* xd = xr + 8 * 257;
  int tid = threadIdx.x;
  int row0 = blockIdx.x * 8;
  for (int i = tid; i < 48 * 256; i += 256) xw[(i >> 8) * 257 + (i & 255)] = xpw[i];
  const float* src = g_xconv + (size_t)row0 * DHALF;
  for (int i = tid; i < 8 * 256; i += 256) xr[(i >> 8) * 257 + (i & 255)] = src[i];
  __syncthreads();
  for (int o = tid; o < 384; o += 256) {
    int r = o / 48, e = o - r * 48;
    const float* xp = xr + r * 257;
    const float* wp = xw + e * 257;
    float s = 0.f;
#pragma unroll 8
    for (int k = 0; k < 256; ++k) s = fmaf(xp[k], wp[k], s);
    xd[r * 48 + e] = s;
  }
  __syncthreads();
  int w = tid >> 5, lane = tid & 31;
  float v0 = xd[w * 48 + lane];
  float v1 = (lane < 16) ? xd[w * 48 + 32 + lane] : 0.f;
  float s = v0 + v1, sq = v0 * v0 + v1 * v1;
#pragma unroll
  for (int off = 16; off > 0; off >>= 1) {
    s  += __shfl_xor_sync(0xffffffffu, s, off);
    sq += __shfl_xor_sync(0xffffffffu, sq, off);
  }
  float mean = s * (1.f / 48.f);
  float var = sq * (1.f / 48.f) - mean * mean;
  float rstd = rsqrtf(var + 1e-5f);
  int grow = row0 + w;
  {
    int e = lane;
    float y = (v0 - mean) * rstd * lnw[e] + lnb[e];
    g_dtin[(size_t)grow * 32 + e] = y;
  }
  if (lane < 16) {
    int e = 32 + lane;
    float y = (v1 - mean) * rstd * lnw[e] + lnb[e];
    g_BC[(size_t)grow * 16 + (e - 32)] = y;
  }
}

/* ---------- dt_proj GEMM: (M x 32) @ (256 x 32)^T -> g_dt ---------- */
__global__ void __launch_bounds__(256) gemm_dt_kernel(const float* __restrict__ dtw) {
  __shared__ __align__(16) float As[8][128];
  __shared__ __align__(16) float Ws[8][128];
  int tid = threadIdx.x;
  int m0 = blockIdx.x * 128, n0 = blockIdx.y * 128;
  float acc[8][8];
#pragma unroll
  for (int i = 0; i < 8; ++i)
#pragma unroll
    for (int j = 0; j < 8; ++j) acc[i][j] = 0.f;
  int ar = tid >> 1, ac = (tid & 1) * 4;
  const float* arow = g_dtin + (size_t)(m0 + ar) * 32 + ac;
  const float* wrow = dtw + (size_t)(n0 + ar) * 32 + ac;
  for (int k0 = 0; k0 < 32; k0 += 8) {
    float4 av = *(const float4*)(arow + k0);
    float4 wv = *(const float4*)(wrow + k0);
    As[ac][ar] = av.x; As[ac+1][ar] = av.y; As[ac+2][ar] = av.z; As[ac+3][ar] = av.w;
    Ws[ac][ar] = wv.x; Ws[ac+1][ar] = wv.y; Ws[ac+2][ar] = wv.z; Ws[ac+3][ar] = wv.w;
    __syncthreads();
    tile_fma(As, Ws, acc, (tid >> 4) * 8, (tid & 15) * 8);
    __syncthreads();
  }
  int tm = (tid >> 4) * 8, tn = (tid & 15) * 8;
#pragma unroll
  for (int i = 0; i < 8; ++i) {
    float* o = g_dt + (size_t)(m0 + tm + i) * DHALF + n0 + tn;
    float4 v0 = {acc[i][0], acc[i][1], acc[i][2], acc[i][3]};
    float4 v1 = {acc[i][4], acc[i][5], acc[i][6], acc[i][7]};
    *(float4*)o = v0; *(float4*)(o + 4) = v1;
  }
}

/* ---------- selective scan ---------- */
__global__ void __launch_bounds__(256) scan_kernel(const float* __restrict__ A_log,
                                                   const float* __restrict__ dtb_v,
                                                   const float* __restrict__ Dp) {
  __shared__ float bc[49 * 16];
  int b = blockIdx.x, d = threadIdx.x;
  for (int i = d; i < 49 * 16; i += 256) bc[i] = g_BC[(size_t)b * 49 * 16 + i];
  __syncthreads();
  float Ar[8];
#pragma unroll
  for (int n = 0; n < 8; ++n) Ar[n] = -expf(A_log[d * 8 + n]);
  float dtb = dtb_v[d], Dv = Dp[d];
  float h[8];
#pragma unroll
  for (int n = 0; n < 8; ++n) h[n] = 0.f;
  const float* dtp = g_dt + (size_t)b * 49 * DHALF + d;
  const float* up  = g_xconv + (size_t)b * 49 * DHALF + d;
  float* yp = g_ycat + (size_t)b * 49 * DIMX + d;
  for (int l = 0; l < 49; ++l) {
    float dtv = dtp[l * DHALF] + dtb;
    dtv = (dtv > 20.f) ? dtv : log1pf(__expf(dtv));
    float u = up[l * DHALF];
    float dbu = dtv * u;
    const float* B = &bc[l * 16];
    float y = 0.f;
#pragma unroll
    for (int n = 0; n < 8; ++n) {
      h[n] = fmaf(h[n], __expf(dtv * Ar[n]), dbu * B[n]);
      y = fmaf(h[n], B[8 + n], y);
    }
    y = fmaf(Dv, u, y);
    if (!isfinite(y)) y = isnan(y) ? 0.f : copysignf(3.402823466e38f, y);
    yp[l * DIMX] = y;
  }
}

/* ------------------- launch ------------------- */
extern "C" void kernel_launch(void* const* d_in, const int* in_sizes, int n_in,
                              void* d_out, int out_size) {
  const float *tokens, *pre_w[4], *pre_b[4], *post_w[4], *post_b[4];
  const float *in_proj_w, *conv_x_w, *conv_x_b, *conv_z_w, *conv_z_b;
  const float *x_proj_w, *ln_w, *ln_b, *dt_proj_w, *dt_proj_b;
  const float *A_log, *D_param, *out_proj_w, *gate_logits;

  tokens = (const float*)d_in[0];
  for (int g = 0; g < 4; ++g) {
    pre_w[g] = (const float*)d_in[1 + 2 * g];
    pre_b[g] = (const float*)d_in[2 + 2 * g];
  }
  if (in_sizes[10] == 768) {
    in_proj_w = (const float*)d_in[9];
    conv_x_w = (const float*)d_in[10]; conv_x_b = (const float*)d_in[11];
    conv_z_w = (const float*)d_in[12]; conv_z_b = (const float*)d_in[13];
    x_proj_w = (const float*)d_in[14];
    ln_w = (const float*)d_in[15]; ln_b = (const float*)d_in[16];
    dt_proj_w = (const float*)d_in[17]; dt_proj_b = (const float*)d_in[18];
    A_log = (const float*)d_in[19]; D_param = (const float*)d_in[20];
    out_proj_w = (const float*)d_in[21];
    for (int g = 0; g < 4; ++g) {
      post_w[g] = (const float*)d_in[22 + 2 * g];
      post_b[g] = (const float*)d_in[23 + 2 * g];
    }
    gate_logits = (const float*)d_in[30];
  } else {
    for (int g = 0; g < 4; ++g) {
      post_w[g] = (const float*)d_in[9 + 2 * g];
      post_b[g] = (const float*)d_in[10 + 2 * g];
    }
    in_proj_w = (const float*)d_in[17];
    conv_x_w = (const float*)d_in[18]; conv_x_b = (const float*)d_in[19];
    conv_z_w = (const float*)d_in[20]; conv_z_b = (const float*)d_in[21];
    x_proj_w = (const float*)d_in[22];
    ln_w = (const float*)d_in[23]; ln_b = (const float*)d_in[24];
    dt_proj_w = (const float*)d_in[25]; dt_proj_b = (const float*)d_in[26];
    A_log = (const float*)d_in[27]; D_param = (const float*)d_in[28];
    out_proj_w = (const float*)d_in[29];
    gate_logits = (const float*)d_in[30];
  }
  float* out = (float*)d_out;

  cudaFuncSetAttribute(xdbl_kernel, cudaFuncAttributeMaxDynamicSharedMemorySize, 60416);
  cudaFuncSetAttribute(gemm_mma<0>, cudaFuncAttributeMaxDynamicSharedMemorySize, SMEM_MM);
  cudaFuncSetAttribute(gemm_mma<1>, cudaFuncAttributeMaxDynamicSharedMemorySize, SMEM_MM);

  /* 1. fold weights */
  NNArgs na;
  for (int g = 0; g < 4; ++g) {
    na.A[g] = in_proj_w;  na.B[g] = pre_w[g];
    na.A[4+g] = post_w[g]; na.B[4+g] = out_proj_w;
  }
  gemm_nn_kernel<<<dim3(4, 4, 8), 256>>>(na);
  split_w_kernel<<<4096, 256>>>();
  bias1_kernel<<<4, 512>>>(in_proj_w, pre_b[0], pre_b[1], pre_b[2], pre_b[3]);
  gates_bias2_kernel<<<1, 512>>>(gate_logits, post_b[0], post_b[1], post_b[2], post_b[3]);

  /* 2. fused pre-proj(+perm) + in_proj (HMMA split-bf16) */
  gemm_mma<0><<<dim3(784, 4), 256, SMEM_MM>>>(tokens, nullptr);

  /* 3. depthwise conv + silu */
  conv_kernel<<<MROWS, 256>>>(conv_x_w, conv_x_b, conv_z_w, conv_z_b);

  /* 4. x_proj + layernorm */
  xdbl_kernel<<<MROWS / 8, 256, 60416>>>(x_proj_w, ln_w, ln_b);

  /* 5. dt_proj */
  gemm_dt_kernel<<<dim3(784, 2), 256>>>(dt_proj_w);

  /* 6. selective scan */
  scan_kernel<<<BTOT, 256>>>(A_log, dt_proj_b, D_param);

  /* 7. fused out_proj + gated post-projections (HMMA split-bf16) */
  gemm_mma<1><<<dim3(196, 4), 256, SMEM_MM>>>(nullptr, out);
}

// round 11
// speedup vs baseline: 2.1912x; 1.1642x over previous
#include <cuda_runtime.h>
#include <cuda_bf16.h>
#include <math.h>
#include <stdint.h>

#define DIMX 512
#define NPOS 49
#define BTOT 2048
#define DHALF 256
#define MROWS 100352    /* BTOT*NPOS */
#define GSTRIDE 25088   /* 512*49 */

/* ------------------- scratch (static, no allocation) ------------------- */
__device__ float g_xz   [(size_t)MROWS * DIMX];
__device__ float g_xconv[(size_t)MROWS * DHALF];
__device__ float g_dtin [(size_t)MROWS * 32];
__device__ float g_BC   [(size_t)MROWS * 16];
__device__ float g_ycat [(size_t)MROWS * DIMX];
__device__ float g_Wc   [4 * DIMX * DIMX];
__device__ float g_bc   [4 * DIMX];
__device__ float g_Wo   [4 * DIMX * DIMX];
__device__ float g_b2   [DIMX];
__device__ float g_gates[4];
__device__ __nv_bfloat16 g_Wc_h[4 * DIMX * DIMX];
__device__ __nv_bfloat16 g_Wc_l[4 * DIMX * DIMX];
__device__ __nv_bfloat16 g_Wo_h[4 * DIMX * DIMX];
__device__ __nv_bfloat16 g_Wo_l[4 * DIMX * DIMX];

/* ------------------- permutation index tables ------------------- */
__constant__ int c_idx[4][49] = {
  { 0,1,2,3,4,5,6,7,8,9,10,11,12,13,14,15,16,17,18,19,20,21,22,23,24,
    25,26,27,28,29,30,31,32,33,34,35,36,37,38,39,40,41,42,43,44,45,46,47,48 },
  { 0,7,14,21,28,35,42, 1,8,15,22,29,36,43, 2,9,16,23,30,37,44,
    3,10,17,24,31,38,45, 4,11,18,25,32,39,46, 5,12,19,26,33,40,47,
    6,13,20,27,34,41,48 },
  { 0, 1,7, 2,8,14, 3,9,15,21, 4,10,16,22,28, 5,11,17,23,29,35,
    6,12,18,24,30,36,42, 13,19,25,31,37,43, 20,26,32,38,44,
    27,33,39,45, 34,40,46, 41,47, 48 },
  { 6, 5,13, 4,12,20, 3,11,19,27, 2,10,18,26,34, 1,9,17,25,33,41,
    0,8,16,24,32,40,48, 7,15,23,31,39,47, 14,22,30,38,46,
    21,29,37,45, 28,36,44, 35,43, 42 }
};

/* ======================= mma.sync helpers ======================= */
__device__ __forceinline__ uint32_t smem_u32(const void* p) {
  uint32_t a;
  asm("{ .reg .u64 t; cvta.to.shared.u64 t, %1; cvt.u32.u64 %0, t; }" : "=r"(a) : "l"(p));
  return a;
}
__device__ __forceinline__ void ldsm4(uint32_t* r, uint32_t addr) {
  asm volatile("ldmatrix.sync.aligned.m8n8.x4.shared.b16 {%0,%1,%2,%3}, [%4];"
               : "=r"(r[0]), "=r"(r[1]), "=r"(r[2]), "=r"(r[3]) : "r"(addr));
}
__device__ __forceinline__ void mma16816(float* c, const uint32_t* a, const uint32_t* b) {
  asm volatile("mma.sync.aligned.m16n8k16.row.col.f32.bf16.bf16.f32 "
               "{%0,%1,%2,%3}, {%4,%5,%6,%7}, {%8,%9}, {%0,%1,%2,%3};"
               : "+f"(c[0]), "+f"(c[1]), "+f"(c[2]), "+f"(c[3])
               : "r"(a[0]), "r"(a[1]), "r"(a[2]), "r"(a[3]), "r"(b[0]), "r"(b[1]));
}

__device__ __forceinline__ void split4(float4 v, uint2& hi, uint2& lo) {
  __nv_bfloat162 h0 = __floats2bfloat162_rn(v.x, v.y);
  __nv_bfloat162 h1 = __floats2bfloat162_rn(v.z, v.w);
  float rx = v.x - __bfloat162float(h0.x);
  float ry = v.y - __bfloat162float(h0.y);
  float rz = v.z - __bfloat162float(h1.x);
  float rw = v.w - __bfloat162float(h1.y);
  __nv_bfloat162 l0 = __floats2bfloat162_rn(rx, ry);
  __nv_bfloat162 l1 = __floats2bfloat162_rn(rz, rw);
  hi.x = *(uint32_t*)&h0; hi.y = *(uint32_t*)&h1;
  lo.x = *(uint32_t*)&l0; lo.y = *(uint32_t*)&l1;
}

/* smem layout (bf16, LDA = 72 elements = 144B rows, conflict-free ldmatrix) */
#define LDA      72
#define OFF_AH   0
#define OFF_AL   18432
#define OFF_BH   36864
#define OFF_BL   55296
#define OFF_ROWP 73728
#define SMEM_MM  74752

/* =================== HMMA split-bf16 GEMM (G2=0: gemm1, G2=1: gemm2) ===================
   NOTE: grid is (bn, bm) — bn fastest so same-A blocks are adjacent for L2 reuse. */
template<int G2>
__global__ void __launch_bounds__(256) gemm_mma(const float* __restrict__ src,
                                                float* __restrict__ dstp) {
  extern __shared__ __align__(16) char sm[];
  const int NCH = G2 ? 32 : 8;
  int tid = threadIdx.x, wid = tid >> 5, lane = tid & 31;
  int warp_m = wid & 3, warp_n = wid >> 2;
  int bm = blockIdx.y, bn = blockIdx.x;
  int m0 = bm * 128, n0 = bn * 128;
  uint32_t smb = smem_u32(sm);

  const float** rowp = (const float**)(sm + OFF_ROWP);
  int g1 = 0;
  if (!G2) {
    g1 = bm / 196;
    if (tid < 128) {
      int m = m0 + tid - g1 * GSTRIDE;
      int b = m / 49, i = m - b * 49;
      rowp[tid] = src + ((size_t)b * 49 + c_idx[g1][i]) * DIMX;
    }
    __syncthreads();
  }

  float acc[2][8][4];
#pragma unroll
  for (int t = 0; t < 2; ++t)
#pragma unroll
    for (int n = 0; n < 8; ++n)
#pragma unroll
      for (int e = 0; e < 4; ++e) acc[t][n][e] = 0.f;

  uint32_t a_row = warp_m * 32 + (lane & 15);
  uint32_t a_coff = (lane >> 4) << 3;
  uint32_t b_row = warp_n * 64 + ((lane >> 4) << 3) + (lane & 7);
  uint32_t b_coff = ((lane >> 3) & 1) << 3;

  for (int c = 0; c < NCH; ++c) {
    int gq = G2 ? (c >> 3) : g1;
    int k0 = (G2 ? (c & 7) : c) * 64;
    const __nv_bfloat16* Wh = (G2 ? g_Wo_h : g_Wc_h) + (size_t)gq * DIMX * DIMX;
    const __nv_bfloat16* Wl = (G2 ? g_Wo_l : g_Wc_l) + (size_t)gq * DIMX * DIMX;
    float gate = G2 ? g_gates[gq] : 1.f;

    __syncthreads();

#pragma unroll
    for (int i = 0; i < 8; ++i) {
      int slot = tid + i * 256;
      int r = slot >> 4, c4 = slot & 15;
      const float* ap = G2 ? (g_ycat + (size_t)(gq * GSTRIDE + m0 + r) * DIMX + k0 + c4 * 4)
                           : (rowp[r] + k0 + c4 * 4);
      float4 v = *(const float4*)ap;
      if (G2) { v.x *= gate; v.y *= gate; v.z *= gate; v.w *= gate; }
      uint2 hi, lo;
      split4(v, hi, lo);
      int off = (r * LDA + c4 * 4) * 2;
      *(uint2*)(sm + OFF_AH + off) = hi;
      *(uint2*)(sm + OFF_AL + off) = lo;
    }
#pragma unroll
    for (int i = 0; i < 8; ++i) {
      int slot = tid + i * 256;
      int plane = slot >> 10, idx = slot & 1023;
      int r = idx >> 3, u = idx & 7;
      const __nv_bfloat16* bp = (plane ? Wl : Wh) + (size_t)(n0 + r) * DIMX + k0 + u * 8;
      uint4 v = *(const uint4*)bp;
      *(uint4*)(sm + (plane ? OFF_BL : OFF_BH) + (r * LDA + u * 8) * 2) = v;
    }
    __syncthreads();

#pragma unroll
    for (int kk = 0; kk < 4; ++kk) {
      int k = kk * 16;
      uint32_t ah[2][4], al[2][4], bh[8][2], bl[8][2];
#pragma unroll
      for (int t = 0; t < 2; ++t) {
        uint32_t off = ((a_row + t * 16) * LDA + k + a_coff) * 2;
        ldsm4(ah[t], smb + OFF_AH + off);
        ldsm4(al[t], smb + OFF_AL + off);
      }
#pragma unroll
      for (int p = 0; p < 4; ++p) {
        uint32_t off = ((b_row + p * 16) * LDA + k + b_coff) * 2;
        uint32_t rh[4], rl[4];
        ldsm4(rh, smb + OFF_BH + off);
        ldsm4(rl, smb + OFF_BL + off);
        bh[2*p][0] = rh[0]; bh[2*p][1] = rh[1]; bh[2*p+1][0] = rh[2]; bh[2*p+1][1] = rh[3];
        bl[2*p][0] = rl[0]; bl[2*p][1] = rl[1]; bl[2*p+1][0] = rl[2]; bl[2*p+1][1] = rl[3];
      }
#pragma unroll
      for (int t = 0; t < 2; ++t)
#pragma unroll
        for (int n = 0; n < 8; ++n) {
          mma16816(acc[t][n], ah[t], bh[n]);
          mma16816(acc[t][n], al[t], bh[n]);
          mma16816(acc[t][n], ah[t], bl[n]);
        }
    }
  }

  const float* bias = (G2 ? g_b2 : g_bc + g1 * DIMX) + n0;
  float* dst = G2 ? dstp : g_xz;
#pragma unroll
  for (int t = 0; t < 2; ++t) {
    int mrow = m0 + warp_m * 32 + t * 16 + (lane >> 2);
#pragma unroll
    for (int n = 0; n < 8; ++n) {
      int cl = warp_n * 64 + n * 8 + (lane & 3) * 2;
      float b0 = bias[cl], b1 = bias[cl + 1];
      float2 v0 = {acc[t][n][0] + b0, acc[t][n][1] + b1};
      float2 v1 = {acc[t][n][2] + b0, acc[t][n][3] + b1};
      *(float2*)(dst + (size_t)mrow * DIMX + n0 + cl) = v0;
      *(float2*)(dst + (size_t)(mrow + 8) * DIMX + n0 + cl) = v1;
    }
  }
}

/* ------------------- fp32 128x128x8 tile microkernel (prep) ------------------- */
__device__ __forceinline__ void tile_fma(const float (&As)[8][128], const float (&Ws)[8][128],
                                         float (&acc)[8][8], int tm, int tn) {
#pragma unroll
  for (int k = 0; k < 8; ++k) {
    float4 a0 = *(const float4*)&As[k][tm];
    float4 a1 = *(const float4*)&As[k][tm + 4];
    float4 w0 = *(const float4*)&Ws[k][tn];
    float4 w1 = *(const float4*)&Ws[k][tn + 4];
    float a[8] = {a0.x,a0.y,a0.z,a0.w,a1.x,a1.y,a1.z,a1.w};
    float w[8] = {w0.x,w0.y,w0.z,w0.w,w1.x,w1.y,w1.z,w1.w};
#pragma unroll
    for (int i = 0; i < 8; ++i)
#pragma unroll
      for (int j = 0; j < 8; ++j)
        acc[i][j] = fmaf(a[i], w[j], acc[i][j]);
  }
}

struct NNArgs { const float* A[8]; const float* B[8]; };

__global__ void __launch_bounds__(256) gemm_nn_kernel(NNArgs args) {
  __shared__ __align__(16) float As[8][128];
  __shared__ __align__(16) float Bs[8][128];
  int tid = threadIdx.x;
  int z = blockIdx.z;
  const float* __restrict__ A = args.A[z];
  const float* __restrict__ B = args.B[z];
  float* __restrict__ C = (z < 4) ? (g_Wc + (size_t)z * DIMX * DIMX)
                                  : (g_Wo + (size_t)(z - 4) * DIMX * DIMX);
  int m0 = blockIdx.x * 128, n0 = blockIdx.y * 128;
  float acc[8][8];
#pragma unroll
  for (int i = 0; i < 8; ++i)
#pragma unroll
    for (int j = 0; j < 8; ++j) acc[i][j] = 0.f;
  int ar = tid >> 1, ac = (tid & 1) * 4;
  int bk = tid >> 5, bn = (tid & 31) * 4;
  for (int k0 = 0; k0 < DIMX; k0 += 8) {
    float4 av = *(const float4*)(A + (size_t)(m0 + ar) * DIMX + k0 + ac);
    float4 bv = *(const float4*)(B + (size_t)(k0 + bk) * DIMX + n0 + bn);
    As[ac][ar] = av.x; As[ac+1][ar] = av.y; As[ac+2][ar] = av.z; As[ac+3][ar] = av.w;
    *(float4*)&Bs[bk][bn] = bv;
    __syncthreads();
    tile_fma(As, Bs, acc, (tid >> 4) * 8, (tid & 15) * 8);
    __syncthreads();
  }
  int tm = (tid >> 4) * 8, tn = (tid & 15) * 8;
#pragma unroll
  for (int i = 0; i < 8; ++i) {
    float* o = C + (size_t)(m0 + tm + i) * DIMX + n0 + tn;
    float4 v0 = {acc[i][0], acc[i][1], acc[i][2], acc[i][3]};
    float4 v1 = {acc[i][4], acc[i][5], acc[i][6], acc[i][7]};
    *(float4*)o = v0; *(float4*)(o + 4) = v1;
  }
}

__global__ void split_w_kernel() {
  size_t i = (size_t)blockIdx.x * blockDim.x + threadIdx.x;
  float w = g_Wc[i];
  __nv_bfloat16 h = __float2bfloat16(w);
  g_Wc_h[i] = h;
  g_Wc_l[i] = __float2bfloat16(w - __bfloat162float(h));
  float w2 = g_Wo[i];
  __nv_bfloat16 h2 = __float2bfloat16(w2);
  g_Wo_h[i] = h2;
  g_Wo_l[i] = __float2bfloat16(w2 - __bfloat162float(h2));
}

__global__ void bias1_kernel(const float* __restrict__ inW,
                             const float* b0, const float* b1,
                             const float* b2, const float* b3) {
  int g = blockIdx.x, o = threadIdx.x;
  const float* pb = (g == 0) ? b0 : (g == 1) ? b1 : (g == 2) ? b2 : b3;
  const float* wr = inW + (size_t)o * DIMX;
  float s = 0.f;
  for (int k = 0; k < DIMX; ++k) s = fmaf(wr[k], pb[k], s);
  g_bc[g * DIMX + o] = s;
}

__global__ void gates_bias2_kernel(const float* __restrict__ gl,
                                   const float* b0, const float* b1,
                                   const float* b2, const float* b3) {
  __shared__ float sg[4];
  int t = threadIdx.x;
  if (t == 0) {
    float a0 = gl[0], a1 = gl[1], a2 = gl[2], a3 = gl[3];
    float m = fmaxf(fmaxf(a0, a1), fmaxf(a2, a3));
    float e0 = __expf(a0 - m), e1 = __expf(a1 - m), e2 = __expf(a2 - m), e3 = __expf(a3 - m);
    float inv = 1.f / (e0 + e1 + e2 + e3);
    sg[0] = e0 * inv; sg[1] = e1 * inv; sg[2] = e2 * inv; sg[3] = e3 * inv;
    g_gates[0] = sg[0]; g_gates[1] = sg[1]; g_gates[2] = sg[2]; g_gates[3] = sg[3];
  }
  __syncthreads();
  g_b2[t] = sg[0]*b0[t] + sg[1]*b1[t] + sg[2]*b2[t] + sg[3]*b3[t];
}

/* ---------- depthwise conv(k=3, SAME) + silu : rolling, 1 block / batch ---------- */
__global__ void __launch_bounds__(512) conv2_kernel(const float* __restrict__ cxw,
                                                    const float* __restrict__ cxb,
                                                    const float* __restrict__ czw,
                                                    const float* __restrict__ czb) {
  int b = blockIdx.x, t = threadIdx.x;
  int d = t & 255;
  bool isz = t >= 256;
  float w0 = isz ? czw[d*3]   : cxw[d*3];
  float w1 = isz ? czw[d*3+1] : cxw[d*3+1];
  float w2 = isz ? czw[d*3+2] : cxw[d*3+2];
  float bb = isz ? czb[d]     : cxb[d];
  const float* base = g_xz + (size_t)b * 49 * DIMX + (isz ? DHALF : 0) + d;
  float* outx = g_xconv + (size_t)b * 49 * DHALF + d;
  float* outz = g_ycat + (size_t)b * 49 * DIMX + DHALF + d;
  float prev = 0.f, cur = base[0], next;
  for (int l = 0; l < 49; ++l) {
    next = (l < 48) ? base[(size_t)(l + 1) * DIMX] : 0.f;
    float v = fmaf(w0, prev, fmaf(w1, cur, fmaf(w2, next, bb)));
    v = v / (1.f + __expf(-v));
    if (isz) outz[(size_t)l * DIMX] = v;
    else     outx[(size_t)l * DHALF] = v;
    prev = cur; cur = next;
  }
}

/* ---------- x_proj GEMM (128x48, K=256) + layernorm(48) fused ---------- */
__global__ void __launch_bounds__(256) xdbl2_kernel(const float* __restrict__ xpw,
                                                    const float* __restrict__ lnw,
                                                    const float* __restrict__ lnb) {
  __shared__ __align__(16) float As[16][132];
  __shared__ __align__(16) float Ws[16][52];
  __shared__ float xd[128][49];
  int tid = threadIdx.x;
  int m0 = blockIdx.x * 128;
  int tm = (tid >> 3) * 4;     /* 32 row-groups of 4 */
  int tn = (tid & 7) * 6;      /* 8 col-groups of 6  */
  float acc[4][6];
#pragma unroll
  for (int i = 0; i < 4; ++i)
#pragma unroll
    for (int j = 0; j < 6; ++j) acc[i][j] = 0.f;

  for (int k0 = 0; k0 < DHALF; k0 += 16) {
#pragma unroll
    for (int i = 0; i < 2; ++i) {
      int fid = tid + i * 256;           /* 0..511 float4s */
      int r = fid >> 2, c4 = fid & 3;
      float4 v = *(const float4*)(g_xconv + (size_t)(m0 + r) * DHALF + k0 + c4 * 4);
      As[c4*4+0][r] = v.x; As[c4*4+1][r] = v.y; As[c4*4+2][r] = v.z; As[c4*4+3][r] = v.w;
    }
    if (tid < 192) {
      int e = tid >> 2, c4 = tid & 3;
      float4 v = *(const float4*)(xpw + (size_t)e * DHALF + k0 + c4 * 4);
      Ws[c4*4+0][e] = v.x; Ws[c4*4+1][e] = v.y; Ws[c4*4+2][e] = v.z; Ws[c4*4+3][e] = v.w;
    }
    __syncthreads();
#pragma unroll
    for (int k = 0; k < 16; ++k) {
      float4 a4 = *(const float4*)&As[k][tm];
      float a[4] = {a4.x, a4.y, a4.z, a4.w};
      float w[6];
#pragma unroll
      for (int j = 0; j < 6; ++j) w[j] = Ws[k][tn + j];
#pragma unroll
      for (int i = 0; i < 4; ++i)
#pragma unroll
        for (int j = 0; j < 6; ++j) acc[i][j] = fmaf(a[i], w[j], acc[i][j]);
    }
    __syncthreads();
  }
#pragma unroll
  for (int i = 0; i < 4; ++i)
#pragma unroll
    for (int j = 0; j < 6; ++j) xd[tm + i][tn + j] = acc[i][j];
  __syncthreads();

  if (tid < 128) {
    float s = 0.f, sq = 0.f;
#pragma unroll
    for (int e = 0; e < 48; ++e) { float v = xd[tid][e]; s += v; sq += v * v; }
    float mean = s * (1.f / 48.f);
    float var = sq * (1.f / 48.f) - mean * mean;
    float rstd = rsqrtf(var + 1e-5f);
    size_t grow = m0 + tid;
    float* dtp = g_dtin + grow * 32;
    float* bcp = g_BC + grow * 16;
#pragma unroll
    for (int e = 0; e < 32; ++e)
      dtp[e] = (xd[tid][e] - mean) * rstd * lnw[e] + lnb[e];
#pragma unroll
    for (int e = 0; e < 16; ++e)
      bcp[e] = (xd[tid][32 + e] - mean) * rstd * lnw[32 + e] + lnb[32 + e];
  }
}

/* ---------- selective scan with fused dt_proj ---------- */
__global__ void __launch_bounds__(256) scan2_kernel(const float* __restrict__ A_log,
                                                    const float* __restrict__ dtb_v,
                                                    const float* __restrict__ Dp,
                                                    const float* __restrict__ dtw) {
  __shared__ float bc[49 * 16];
  __shared__ float sdt[49 * 32];
  int b = blockIdx.x, d = threadIdx.x;
  for (int i = d; i < 49 * 16; i += 256) bc[i] = g_BC[(size_t)b * 49 * 16 + i];
  for (int i = d; i < 49 * 32; i += 256) sdt[i] = g_dtin[(size_t)b * 49 * 32 + i];
  __syncthreads();
  float wv[32];
#pragma unroll
  for (int j = 0; j < 8; ++j) {
    float4 v = *(const float4*)(dtw + (size_t)d * 32 + j * 4);
    wv[j*4] = v.x; wv[j*4+1] = v.y; wv[j*4+2] = v.z; wv[j*4+3] = v.w;
  }
  float Ar[8];
#pragma unroll
  for (int n = 0; n < 8; ++n) Ar[n] = -expf(A_log[d * 8 + n]);
  float dtb = dtb_v[d], Dv = Dp[d];
  float h[8];
#pragma unroll
  for (int n = 0; n < 8; ++n) h[n] = 0.f;
  const float* up = g_xconv + (size_t)b * 49 * DHALF + d;
  float* yp = g_ycat + (size_t)b * 49 * DIMX + d;
  for (int l = 0; l < 49; ++l) {
    const float* dl = &sdt[l * 32];
    float dtv = dtb;
#pragma unroll
    for (int k = 0; k < 32; ++k) dtv = fmaf(wv[k], dl[k], dtv);
    dtv = (dtv > 20.f) ? dtv : log1pf(__expf(dtv));
    float u = up[l * DHALF];
    float dbu = dtv * u;
    const float* B = &bc[l * 16];
    float y = 0.f;
#pragma unroll
    for (int n = 0; n < 8; ++n) {
      h[n] = fmaf(h[n], __expf(dtv * Ar[n]), dbu * B[n]);
      y = fmaf(h[n], B[8 + n], y);
    }
    y = fmaf(Dv, u, y);
    if (!isfinite(y)) y = isnan(y) ? 0.f : copysignf(3.402823466e38f, y);
    yp[l * DIMX] = y;
  }
}

/* ------------------- launch ------------------- */
extern "C" void kernel_launch(void* const* d_in, const int* in_sizes, int n_in,
                              void* d_out, int out_size) {
  const float *tokens, *pre_w[4], *pre_b[4], *post_w[4], *post_b[4];
  const float *in_proj_w, *conv_x_w, *conv_x_b, *conv_z_w, *conv_z_b;
  const float *x_proj_w, *ln_w, *ln_b, *dt_proj_w, *dt_proj_b;
  const float *A_log, *D_param, *out_proj_w, *gate_logits;

  tokens = (const float*)d_in[0];
  for (int g = 0; g < 4; ++g) {
    pre_w[g] = (const float*)d_in[1 + 2 * g];
    pre_b[g] = (const float*)d_in[2 + 2 * g];
  }
  if (in_sizes[10] == 768) {
    in_proj_w = (const float*)d_in[9];
    conv_x_w = (const float*)d_in[10]; conv_x_b = (const float*)d_in[11];
    conv_z_w = (const float*)d_in[12]; conv_z_b = (const float*)d_in[13];
    x_proj_w = (const float*)d_in[14];
    ln_w = (const float*)d_in[15]; ln_b = (const float*)d_in[16];
    dt_proj_w = (const float*)d_in[17]; dt_proj_b = (const float*)d_in[18];
    A_log = (const float*)d_in[19]; D_param = (const float*)d_in[20];
    out_proj_w = (const float*)d_in[21];
    for (int g = 0; g < 4; ++g) {
      post_w[g] = (const float*)d_in[22 + 2 * g];
      post_b[g] = (const float*)d_in[23 + 2 * g];
    }
    gate_logits = (const float*)d_in[30];
  } else {
    for (int g = 0; g < 4; ++g) {
      post_w[g] = (const float*)d_in[9 + 2 * g];
      post_b[g] = (const float*)d_in[10 + 2 * g];
    }
    in_proj_w = (const float*)d_in[17];
    conv_x_w = (const float*)d_in[18]; conv_x_b = (const float*)d_in[19];
    conv_z_w = (const float*)d_in[20]; conv_z_b = (const float*)d_in[21];
    x_proj_w = (const float*)d_in[22];
    ln_w = (const float*)d_in[23]; ln_b = (const float*)d_in[24];
    dt_proj_w = (const float*)d_in[25]; dt_proj_b = (const float*)d_in[26];
    A_log = (const float*)d_in[27]; D_param = (const float*)d_in[28];
    out_proj_w = (const float*)d_in[29];
    gate_logits = (const float*)d_in[30];
  }
  float* out = (float*)d_out;

  cudaFuncSetAttribute(gemm_mma<0>, cudaFuncAttributeMaxDynamicSharedMemorySize, SMEM_MM);
  cudaFuncSetAttribute(gemm_mma<1>, cudaFuncAttributeMaxDynamicSharedMemorySize, SMEM_MM);

  /* 1. fold weights */
  NNArgs na;
  for (int g = 0; g < 4; ++g) {
    na.A[g] = in_proj_w;  na.B[g] = pre_w[g];
    na.A[4+g] = post_w[g]; na.B[4+g] = out_proj_w;
  }
  gemm_nn_kernel<<<dim3(4, 4, 8), 256>>>(na);
  split_w_kernel<<<4096, 256>>>();
  bias1_kernel<<<4, 512>>>(in_proj_w, pre_b[0], pre_b[1], pre_b[2], pre_b[3]);
  gates_bias2_kernel<<<1, 512>>>(gate_logits, post_b[0], post_b[1], post_b[2], post_b[3]);

  /* 2. fused pre-proj(+perm) + in_proj (HMMA split-bf16; bn fastest for L2 A-reuse) */
  gemm_mma<0><<<dim3(4, 784), 256, SMEM_MM>>>(tokens, nullptr);

  /* 3. depthwise conv + silu, rolling */
  conv2_kernel<<<BTOT, 512>>>(conv_x_w, conv_x_b, conv_z_w, conv_z_b);

  /* 4. x_proj GEMM + layernorm fused */
  xdbl2_kernel<<<MROWS / 128, 256>>>(x_proj_w, ln_w, ln_b);

  /* 5. selective scan with fused dt_proj */
  scan2_kernel<<<BTOT, 256>>>(A_log, dt_proj_b, D_param, dt_proj_w);

  /* 6. fused out_proj + gated post-projections (HMMA split-bf16) */
  gemm_mma<1><<<dim3(4, 196), 256, SMEM_MM>>>(nullptr, out);
}

// round 13
// speedup vs baseline: 2.3007x; 1.0500x over previous
#include <cuda_runtime.h>
#include <cuda_bf16.h>
#include <math.h>
#include <stdint.h>

#define DIMX 512
#define NPOS 49
#define BTOT 2048
#define DHALF 256
#define MROWS 100352    /* BTOT*NPOS */
#define GSTRIDE 25088   /* 512*49 */
#define TOKN 12845056   /* 512*49*512 */

/* ------------------- scratch (static, no allocation) ------------------- */
__device__ float g_xz   [(size_t)MROWS * DIMX];
__device__ float g_xconv[(size_t)MROWS * DHALF];
__device__ float g_dtin [(size_t)MROWS * 32];
__device__ float g_BC   [(size_t)MROWS * 16];
__device__ float g_bc   [4 * DIMX];
__device__ float g_b2   [DIMX];
__device__ float g_gates[4];
/* bf16 hi/lo planes */
__device__ __nv_bfloat16 g_tok_h[TOKN];
__device__ __nv_bfloat16 g_tok_l[TOKN];
__device__ __nv_bfloat16 g_y_h[(size_t)MROWS * DIMX];
__device__ __nv_bfloat16 g_y_l[(size_t)MROWS * DIMX];
__device__ __nv_bfloat16 g_Wc_h[4 * DIMX * DIMX];
__device__ __nv_bfloat16 g_Wc_l[4 * DIMX * DIMX];
__device__ __nv_bfloat16 g_Wo_h[4 * DIMX * DIMX];
__device__ __nv_bfloat16 g_Wo_l[4 * DIMX * DIMX];

/* ------------------- permutation index tables ------------------- */
__constant__ int c_idx[4][49] = {
  { 0,1,2,3,4,5,6,7,8,9,10,11,12,13,14,15,16,17,18,19,20,21,22,23,24,
    25,26,27,28,29,30,31,32,33,34,35,36,37,38,39,40,41,42,43,44,45,46,47,48 },
  { 0,7,14,21,28,35,42, 1,8,15,22,29,36,43, 2,9,16,23,30,37,44,
    3,10,17,24,31,38,45, 4,11,18,25,32,39,46, 5,12,19,26,33,40,47,
    6,13,20,27,34,41,48 },
  { 0, 1,7, 2,8,14, 3,9,15,21, 4,10,16,22,28, 5,11,17,23,29,35,
    6,12,18,24,30,36,42, 13,19,25,31,37,43, 20,26,32,38,44,
    27,33,39,45, 34,40,46, 41,47, 48 },
  { 6, 5,13, 4,12,20, 3,11,19,27, 2,10,18,26,34, 1,9,17,25,33,41,
    0,8,16,24,32,40,48, 7,15,23,31,39,47, 14,22,30,38,46,
    21,29,37,45, 28,36,44, 35,43, 42 }
};

/* ======================= asm helpers ======================= */
__device__ __forceinline__ uint32_t smem_u32(const void* p) {
  uint32_t a;
  asm("{ .reg .u64 t; cvta.to.shared.u64 t, %1; cvt.u32.u64 %0, t; }" : "=r"(a) : "l"(p));
  return a;
}
__device__ __forceinline__ void ldsm4(uint32_t* r, uint32_t addr) {
  asm volatile("ldmatrix.sync.aligned.m8n8.x4.shared.b16 {%0,%1,%2,%3}, [%4];"
               : "=r"(r[0]), "=r"(r[1]), "=r"(r[2]), "=r"(r[3]) : "r"(addr));
}
__device__ __forceinline__ void mma16816(float* c, const uint32_t* a, const uint32_t* b) {
  asm volatile("mma.sync.aligned.m16n8k16.row.col.f32.bf16.bf16.f32 "
               "{%0,%1,%2,%3}, {%4,%5,%6,%7}, {%8,%9}, {%0,%1,%2,%3};"
               : "+f"(c[0]), "+f"(c[1]), "+f"(c[2]), "+f"(c[3])
               : "r"(a[0]), "r"(a[1]), "r"(a[2]), "r"(a[3]), "r"(b[0]), "r"(b[1]));
}
__device__ __forceinline__ void cpasync16(uint32_t dst, const void* src) {
  asm volatile("cp.async.cg.shared.global [%0], [%1], 16;" :: "r"(dst), "l"(src));
}
__device__ __forceinline__ void cpcommit() { asm volatile("cp.async.commit_group;" ::: "memory"); }
template<int N> __device__ __forceinline__ void cpwait() {
  asm volatile("cp.async.wait_group %0;" :: "n"(N) : "memory");
}

__device__ __forceinline__ void split4(float4 v, uint2& hi, uint2& lo) {
  __nv_bfloat162 h0 = __floats2bfloat162_rn(v.x, v.y);
  __nv_bfloat162 h1 = __floats2bfloat162_rn(v.z, v.w);
  float rx = v.x - __bfloat162float(h0.x);
  float ry = v.y - __bfloat162float(h0.y);
  float rz = v.z - __bfloat162float(h1.x);
  float rw = v.w - __bfloat162float(h1.y);
  __nv_bfloat162 l0 = __floats2bfloat162_rn(rx, ry);
  __nv_bfloat162 l1 = __floats2bfloat162_rn(rz, rw);
  hi.x = *(uint32_t*)&h0; hi.y = *(uint32_t*)&h1;
  lo.x = *(uint32_t*)&l0; lo.y = *(uint32_t*)&l1;
}

/* smem: 2 stages x 4 planes x (128 rows x 144B) */
#define LDA      72          /* elements; 144 B row pitch */
#define PLANE_B  18432
#define STAGE_B  73728       /* AH | AL | BH | BL */
#define P_AH     0
#define P_AL     18432
#define P_BH     36864
#define P_BL     55296
#define OFF_AOFF 147456      /* 128 ints: row offsets for A gather */
#define SMEM_MM  148480

/* =================== cp.async-pipelined HMMA split-bf16 GEMM =================== */
template<int G2>
__global__ void __launch_bounds__(256) gemm_mma(float* __restrict__ dstp) {
  extern __shared__ __align__(16) char sm[];
  const int NCH = G2 ? 32 : 8;
  int tid = threadIdx.x, wid = tid >> 5, lane = tid & 31;
  int warp_m = wid & 3, warp_n = wid >> 2;
  int bm = blockIdx.y, bn = blockIdx.x;
  int m0 = bm * 128, n0 = bn * 128;
  uint32_t smb = smem_u32(sm);

  int* aoff = (int*)(sm + OFF_AOFF);
  int g1 = 0;
  if (!G2) {
    g1 = bm / 196;
    if (tid < 128) {
      int m = m0 + tid - g1 * GSTRIDE;
      int b = m / 49, i = m - b * 49;
      aoff[tid] = (b * 49 + c_idx[g1][i]) * DIMX;
    }
    __syncthreads();
  }

  const __nv_bfloat16* Wh_base = G2 ? g_Wo_h : g_Wc_h;
  const __nv_bfloat16* Wl_base = G2 ? g_Wo_l : g_Wc_l;

  /* prefetch chunk into stage s */
  auto prefetch = [&](int c) {
    int s = c & 1;
    int gq = G2 ? (c >> 3) : g1;
    int k0 = (G2 ? (c & 7) : c) * 64;
    uint32_t stg = smb + s * STAGE_B;
    const __nv_bfloat16* ah;
    const __nv_bfloat16* al;
    const __nv_bfloat16* wh = Wh_base + ((size_t)gq * DIMX + n0) * DIMX + k0;
    const __nv_bfloat16* wl = Wl_base + ((size_t)gq * DIMX + n0) * DIMX + k0;
    if (G2) {
      ah = g_y_h + (size_t)(gq * GSTRIDE + m0) * DIMX + k0;
      al = g_y_l + (size_t)(gq * GSTRIDE + m0) * DIMX + k0;
    } else {
      ah = g_tok_h + k0;
      al = g_tok_l + k0;
    }
#pragma unroll
    for (int i = 0; i < 4; ++i) {
      int idx = tid + i * 256;
      int r = idx >> 3, j = idx & 7;
      uint32_t d = stg + r * 144 + j * 16;
      size_t arow = G2 ? (size_t)r * DIMX : (size_t)aoff[r];
      cpasync16(d + P_AH, ah + arow + j * 8);
      cpasync16(d + P_AL, al + arow + j * 8);
      cpasync16(d + P_BH, wh + (size_t)r * DIMX + j * 8);
      cpasync16(d + P_BL, wl + (size_t)r * DIMX + j * 8);
    }
  };

  float acc[2][8][4];
#pragma unroll
  for (int t = 0; t < 2; ++t)
#pragma unroll
    for (int n = 0; n < 8; ++n)
#pragma unroll
      for (int e = 0; e < 4; ++e) acc[t][n][e] = 0.f;

  uint32_t a_row = warp_m * 32 + (lane & 15);
  uint32_t a_coff = (lane >> 4) << 3;
  uint32_t b_row = warp_n * 64 + ((lane >> 4) << 3) + (lane & 7);
  uint32_t b_coff = ((lane >> 3) & 1) << 3;

  prefetch(0); cpcommit();

  for (int c = 0; c < NCH; ++c) {
    if (c + 1 < NCH) { prefetch(c + 1); cpcommit(); cpwait<1>(); }
    else             { cpwait<0>(); }
    __syncthreads();
    uint32_t stg = smb + (c & 1) * STAGE_B;
#pragma unroll
    for (int kk = 0; kk < 4; ++kk) {
      int k = kk * 16;
      uint32_t ah[2][4], al[2][4], bh[8][2], bl[8][2];
#pragma unroll
      for (int t = 0; t < 2; ++t) {
        uint32_t off = ((a_row + t * 16) * LDA + k + a_coff) * 2;
        ldsm4(ah[t], stg + P_AH + off);
        ldsm4(al[t], stg + P_AL + off);
      }
#pragma unroll
      for (int p = 0; p < 4; ++p) {
        uint32_t off = ((b_row + p * 16) * LDA + k + b_coff) * 2;
        uint32_t rh[4], rl[4];
        ldsm4(rh, stg + P_BH + off);
        ldsm4(rl, stg + P_BL + off);
        bh[2*p][0] = rh[0]; bh[2*p][1] = rh[1]; bh[2*p+1][0] = rh[2]; bh[2*p+1][1] = rh[3];
        bl[2*p][0] = rl[0]; bl[2*p][1] = rl[1]; bl[2*p+1][0] = rl[2]; bl[2*p+1][1] = rl[3];
      }
#pragma unroll
      for (int t = 0; t < 2; ++t)
#pragma unroll
        for (int n = 0; n < 8; ++n) {
          mma16816(acc[t][n], ah[t], bh[n]);
          mma16816(acc[t][n], al[t], bh[n]);
          mma16816(acc[t][n], ah[t], bl[n]);
        }
    }
    __syncthreads();
  }

  const float* bias = (G2 ? g_b2 : g_bc + g1 * DIMX) + n0;
  float* dst = G2 ? dstp : g_xz;
#pragma unroll
  for (int t = 0; t < 2; ++t) {
    int mrow = m0 + warp_m * 32 + t * 16 + (lane >> 2);
#pragma unroll
    for (int n = 0; n < 8; ++n) {
      int cl = warp_n * 64 + n * 8 + (lane & 3) * 2;
      float b0 = bias[cl], b1 = bias[cl + 1];
      float2 v0 = {acc[t][n][0] + b0, acc[t][n][1] + b1};
      float2 v1 = {acc[t][n][2] + b0, acc[t][n][3] + b1};
      *(float2*)(dst + (size_t)mrow * DIMX + n0 + cl) = v0;
      *(float2*)(dst + (size_t)(mrow + 8) * DIMX + n0 + cl) = v1;
    }
  }
}

/* ------------------- fp32 prep GEMM: folds weights, emits bf16 planes ------------------- */
__device__ __forceinline__ void tile_fma(const float (&As)[8][128], const float (&Ws)[8][128],
                                         float (&acc)[8][8], int tm, int tn) {
#pragma unroll
  for (int k = 0; k < 8; ++k) {
    float4 a0 = *(const float4*)&As[k][tm];
    float4 a1 = *(const float4*)&As[k][tm + 4];
    float4 w0 = *(const float4*)&Ws[k][tn];
    float4 w1 = *(const float4*)&Ws[k][tn + 4];
    float a[8] = {a0.x,a0.y,a0.z,a0.w,a1.x,a1.y,a1.z,a1.w};
    float w[8] = {w0.x,w0.y,w0.z,w0.w,w1.x,w1.y,w1.z,w1.w};
#pragma unroll
    for (int i = 0; i < 8; ++i)
#pragma unroll
      for (int j = 0; j < 8; ++j)
        acc[i][j] = fmaf(a[i], w[j], acc[i][j]);
  }
}

struct NNArgs { const float* A[8]; const float* B[8]; };

__global__ void __launch_bounds__(256) gemm_nn_kernel(NNArgs args) {
  __shared__ __align__(16) float As[8][128];
  __shared__ __align__(16) float Bs[8][128];
  int tid = threadIdx.x;
  int z = blockIdx.z;
  const float* __restrict__ A = args.A[z];
  const float* __restrict__ B = args.B[z];
  __nv_bfloat16* Ch = (z < 4) ? (g_Wc_h + (size_t)z * DIMX * DIMX)
                              : (g_Wo_h + (size_t)(z - 4) * DIMX * DIMX);
  __nv_bfloat16* Cl = (z < 4) ? (g_Wc_l + (size_t)z * DIMX * DIMX)
                              : (g_Wo_l + (size_t)(z - 4) * DIMX * DIMX);
  float gate = (z < 4) ? 1.f : g_gates[z - 4];
  int m0 = blockIdx.x * 128, n0 = blockIdx.y * 128;
  float acc[8][8];
#pragma unroll
  for (int i = 0; i < 8; ++i)
#pragma unroll
    for (int j = 0; j < 8; ++j) acc[i][j] = 0.f;
  int ar = tid >> 1, ac = (tid & 1) * 4;
  int bk = tid >> 5, bn = (tid & 31) * 4;
  for (int k0 = 0; k0 < DIMX; k0 += 8) {
    float4 av = *(const float4*)(A + (size_t)(m0 + ar) * DIMX + k0 + ac);
    float4 bv = *(const float4*)(B + (size_t)(k0 + bk) * DIMX + n0 + bn);
    As[ac][ar] = av.x; As[ac+1][ar] = av.y; As[ac+2][ar] = av.z; As[ac+3][ar] = av.w;
    *(float4*)&Bs[bk][bn] = bv;
    __syncthreads();
    tile_fma(As, Bs, acc, (tid >> 4) * 8, (tid & 15) * 8);
    __syncthreads();
  }
  int tm = (tid >> 4) * 8, tn = (tid & 15) * 8;
#pragma unroll
  for (int i = 0; i < 8; ++i) {
    size_t base = (size_t)(m0 + tm + i) * DIMX + n0 + tn;
#pragma unroll
    for (int j = 0; j < 8; j += 4) {
      float4 v = {acc[i][j] * gate, acc[i][j+1] * gate, acc[i][j+2] * gate, acc[i][j+3] * gate};
      uint2 hi, lo;
      split4(v, hi, lo);
      *(uint2*)(Ch + base + j) = hi;
      *(uint2*)(Cl + base + j) = lo;
    }
  }
}

/* ---------- tokens -> bf16 hi/lo planes ---------- */
__global__ void __launch_bounds__(256) tok_split_kernel(const float* __restrict__ tokens) {
  size_t i4 = ((size_t)blockIdx.x * blockDim.x + threadIdx.x) * 4;
  float4 v = *(const float4*)(tokens + i4);
  uint2 hi, lo;
  split4(v, hi, lo);
  *(uint2*)(g_tok_h + i4) = hi;
  *(uint2*)(g_tok_l + i4) = lo;
}

__global__ void bias1_kernel(const float* __restrict__ inW,
                             const float* b0, const float* b1,
                             const float* b2, const float* b3) {
  int g = blockIdx.x, o = threadIdx.x;
  const float* pb = (g == 0) ? b0 : (g == 1) ? b1 : (g == 2) ? b2 : b3;
  const float* wr = inW + (size_t)o * DIMX;
  float s = 0.f;
  for (int k = 0; k < DIMX; ++k) s = fmaf(wr[k], pb[k], s);
  g_bc[g * DIMX + o] = s;
}

__global__ void gates_bias2_kernel(const float* __restrict__ gl,
                                   const float* b0, const float* b1,
                                   const float* b2, const float* b3) {
  __shared__ float sg[4];
  int t = threadIdx.x;
  if (t == 0) {
    float a0 = gl[0], a1 = gl[1], a2 = gl[2], a3 = gl[3];
    float m = fmaxf(fmaxf(a0, a1), fmaxf(a2, a3));
    float e0 = __expf(a0 - m), e1 = __expf(a1 - m), e2 = __expf(a2 - m), e3 = __expf(a3 - m);
    float inv = 1.f / (e0 + e1 + e2 + e3);
    sg[0] = e0 * inv; sg[1] = e1 * inv; sg[2] = e2 * inv; sg[3] = e3 * inv;
    g_gates[0] = sg[0]; g_gates[1] = sg[1]; g_gates[2] = sg[2]; g_gates[3] = sg[3];
  }
  __syncthreads();
  g_b2[t] = sg[0]*b0[t] + sg[1]*b1[t] + sg[2]*b2[t] + sg[3]*b3[t];
}

/* ---------- depthwise conv(k=3) + silu: rolling; z half -> bf16 planes ---------- */
__global__ void __launch_bounds__(512) conv2_kernel(const float* __restrict__ cxw,
                                                    const float* __restrict__ cxb,
                                                    const float* __restrict__ czw,
                                                    const float* __restrict__ czb) {
  int b = blockIdx.x, t = threadIdx.x;
  int d = t & 255;
  bool isz = t >= 256;
  float w0 = isz ? czw[d*3]   : cxw[d*3];
  float w1 = isz ? czw[d*3+1] : cxw[d*3+1];
  float w2 = isz ? czw[d*3+2] : cxw[d*3+2];
  float bb = isz ? czb[d]     : cxb[d];
  const float* base = g_xz + (size_t)b * 49 * DIMX + (isz ? DHALF : 0) + d;
  float* outx = g_xconv + (size_t)b * 49 * DHALF + d;
  size_t zoff = (size_t)b * 49 * DIMX + DHALF + d;
  float prev = 0.f, cur = base[0], next;
  for (int l = 0; l < 49; ++l) {
    next = (l < 48) ? base[(size_t)(l + 1) * DIMX] : 0.f;
    float v = fmaf(w0, prev, fmaf(w1, cur, fmaf(w2, next, bb)));
    v = v / (1.f + __expf(-v));
    if (isz) {
      __nv_bfloat16 h = __float2bfloat16(v);
      g_y_h[zoff + (size_t)l * DIMX] = h;
      g_y_l[zoff + (size_t)l * DIMX] = __float2bfloat16(v - __bfloat162float(h));
    } else {
      outx[(size_t)l * DHALF] = v;
    }
    prev = cur; cur = next;
  }
}

/* ---------- x_proj GEMM (128x48, K=256) + layernorm(48) fused ---------- */
__global__ void __launch_bounds__(256) xdbl2_kernel(const float* __restrict__ xpw,
                                                    const float* __restrict__ lnw,
                                                    const float* __restrict__ lnb) {
  __shared__ __align__(16) float As[16][132];
  __shared__ __align__(16) float Ws[16][52];
  __shared__ float xd[128][49];
  int tid = threadIdx.x;
  int m0 = blockIdx.x * 128;
  int tm = (tid >> 3) * 4;
  int tn = (tid & 7) * 6;
  float acc[4][6];
#pragma unroll
  for (int i = 0; i < 4; ++i)
#pragma unroll
    for (int j = 0; j < 6; ++j) acc[i][j] = 0.f;

  for (int k0 = 0; k0 < DHALF; k0 += 16) {
#pragma unroll
    for (int i = 0; i < 2; ++i) {
      int fid = tid + i * 256;
      int r = fid >> 2, c4 = fid & 3;
      float4 v = *(const float4*)(g_xconv + (size_t)(m0 + r) * DHALF + k0 + c4 * 4);
      As[c4*4+0][r] = v.x; As[c4*4+1][r] = v.y; As[c4*4+2][r] = v.z; As[c4*4+3][r] = v.w;
    }
    if (tid < 192) {
      int e = tid >> 2, c4 = tid & 3;
      float4 v = *(const float4*)(xpw + (size_t)e * DHALF + k0 + c4 * 4);
      Ws[c4*4+0][e] = v.x; Ws[c4*4+1][e] = v.y; Ws[c4*4+2][e] = v.z; Ws[c4*4+3][e] = v.w;
    }
    __syncthreads();
#pragma unroll
    for (int k = 0; k < 16; ++k) {
      float4 a4 = *(const float4*)&As[k][tm];
      float a[4] = {a4.x, a4.y, a4.z, a4.w};
      float w[6];
#pragma unroll
      for (int j = 0; j < 6; ++j) w[j] = Ws[k][tn + j];
#pragma unroll
      for (int i = 0; i < 4; ++i)
#pragma unroll
        for (int j = 0; j < 6; ++j) acc[i][j] = fmaf(a[i], w[j], acc[i][j]);
    }
    __syncthreads();
  }
#pragma unroll
  for (int i = 0; i < 4; ++i)
#pragma unroll
    for (int j = 0; j < 6; ++j) xd[tm + i][tn + j] = acc[i][j];
  __syncthreads();

  if (tid < 128) {
    float s = 0.f, sq = 0.f;
#pragma unroll
    for (int e = 0; e < 48; ++e) { float v = xd[tid][e]; s += v; sq += v * v; }
    float mean = s * (1.f / 48.f);
    float var = sq * (1.f / 48.f) - mean * mean;
    float rstd = rsqrtf(var + 1e-5f);
    size_t grow = m0 + tid;
    float* dtp = g_dtin + grow * 32;
    float* bcp = g_BC + grow * 16;
#pragma unroll
    for (int e = 0; e < 32; ++e)
      dtp[e] = (xd[tid][e] - mean) * rstd * lnw[e] + lnb[e];
#pragma unroll
    for (int e = 0; e < 16; ++e)
      bcp[e] = (xd[tid][32 + e] - mean) * rstd * lnw[32 + e] + lnb[32 + e];
  }
}

/* ---------- selective scan w/ fused dt_proj; y -> bf16 planes ---------- */
__global__ void __launch_bounds__(256) scan2_kernel(const float* __restrict__ A_log,
                                                    const float* __restrict__ dtb_v,
                                                    const float* __restrict__ Dp,
                                                    const float* __restrict__ dtw) {
  __shared__ float bc[49 * 16];
  __shared__ float sdt[49 * 32];
  int b = blockIdx.x, d = threadIdx.x;
  for (int i = d; i < 49 * 16; i += 256) bc[i] = g_BC[(size_t)b * 49 * 16 + i];
  for (int i = d; i < 49 * 32; i += 256) sdt[i] = g_dtin[(size_t)b * 49 * 32 + i];
  __syncthreads();
  float wv[32];
#pragma unroll
  for (int j = 0; j < 8; ++j) {
    float4 v = *(const float4*)(dtw + (size_t)d * 32 + j * 4);
    wv[j*4] = v.x; wv[j*4+1] = v.y; wv[j*4+2] = v.z; wv[j*4+3] = v.w;
  }
  float Ar[8];
#pragma unroll
  for (int n = 0; n < 8; ++n) Ar[n] = -expf(A_log[d * 8 + n]);
  float dtb = dtb_v[d], Dv = Dp[d];
  float h[8];
#pragma unroll
  for (int n = 0; n < 8; ++n) h[n] = 0.f;
  const float* up = g_xconv + (size_t)b * 49 * DHALF + d;
  size_t yoff = (size_t)b * 49 * DIMX + d;
  for (int l = 0; l < 49; ++l) {
    const float* dl = &sdt[l * 32];
    float dtv = dtb;
#pragma unroll
    for (int k = 0; k < 32; ++k) dtv = fmaf(wv[k], dl[k], dtv);
    dtv = (dtv > 20.f) ? dtv : log1pf(__expf(dtv));
    float u = up[l * DHALF];
    float dbu = dtv * u;
    const float* B = &bc[l * 16];
    float y = 0.f;
#pragma unroll
    for (int n = 0; n < 8; ++n) {
      h[n] = fmaf(h[n], __expf(dtv * Ar[n]), dbu * B[n]);
      y = fmaf(h[n], B[8 + n], y);
    }
    y = fmaf(Dv, u, y);
    if (!isfinite(y)) y = isnan(y) ? 0.f : copysignf(3.402823466e38f, y);
    __nv_bfloat16 hh = __float2bfloat16(y);
    g_y_h[yoff + (size_t)l * DIMX] = hh;
    g_y_l[yoff + (size_t)l * DIMX] = __float2bfloat16(y - __bfloat162float(hh));
  }
}

/* ------------------- launch ------------------- */
extern "C" void kernel_launch(void* const* d_in, const int* in_sizes, int n_in,
                              void* d_out, int out_size) {
  const float *tokens, *pre_w[4], *pre_b[4], *post_w[4], *post_b[4];
  const float *in_proj_w, *conv_x_w, *conv_x_b, *conv_z_w, *conv_z_b;
  const float *x_proj_w, *ln_w, *ln_b, *dt_proj_w, *dt_proj_b;
  const float *A_log, *D_param, *out_proj_w, *gate_logits;

  tokens = (const float*)d_in[0];
  for (int g = 0; g < 4; ++g) {
    pre_w[g] = (const float*)d_in[1 + 2 * g];
    pre_b[g] = (const float*)d_in[2 + 2 * g];
  }
  if (in_sizes[10] == 768) {
    in_proj_w = (const float*)d_in[9];
    conv_x_w = (const float*)d_in[10]; conv_x_b = (const float*)d_in[11];
    conv_z_w = (const float*)d_in[12]; conv_z_b = (const float*)d_in[13];
    x_proj_w = (const float*)d_in[14];
    ln_w = (const float*)d_in[15]; ln_b = (const float*)d_in[16];
    dt_proj_w = (const float*)d_in[17]; dt_proj_b = (const float*)d_in[18];
    A_log = (const float*)d_in[19]; D_param = (const float*)d_in[20];
    out_proj_w = (const float*)d_in[21];
    for (int g = 0; g < 4; ++g) {
      post_w[g] = (const float*)d_in[22 + 2 * g];
      post_b[g] = (const float*)d_in[23 + 2 * g];
    }
    gate_logits = (const float*)d_in[30];
  } else {
    for (int g = 0; g < 4; ++g) {
      post_w[g] = (const float*)d_in[9 + 2 * g];
      post_b[g] = (const float*)d_in[10 + 2 * g];
    }
    in_proj_w = (const float*)d_in[17];
    conv_x_w = (const float*)d_in[18]; conv_x_b = (const float*)d_in[19];
    conv_z_w = (const float*)d_in[20]; conv_z_b = (const float*)d_in[21];
    x_proj_w = (const float*)d_in[22];
    ln_w = (const float*)d_in[23]; ln_b = (const float*)d_in[24];
    dt_proj_w = (const float*)d_in[25]; dt_proj_b = (const float*)d_in[26];
    A_log = (const float*)d_in[27]; D_param = (const float*)d_in[28];
    out_proj_w = (const float*)d_in[29];
    gate_logits = (const float*)d_in[30];
  }
  float* out = (float*)d_out;

  cudaFuncSetAttribute(gemm_mma<0>, cudaFuncAttributeMaxDynamicSharedMemorySize, SMEM_MM);
  cudaFuncSetAttribute(gemm_mma<1>, cudaFuncAttributeMaxDynamicSharedMemorySize, SMEM_MM);

  /* 1. gates first (gemm_nn folds gate into Wo planes), then weight folding */
  gates_bias2_kernel<<<1, 512>>>(gate_logits, post_b[0], post_b[1], post_b[2], post_b[3]);
  NNArgs na;
  for (int g = 0; g < 4; ++g) {
    na.A[g] = in_proj_w;  na.B[g] = pre_w[g];
    na.A[4+g] = post_w[g]; na.B[4+g] = out_proj_w;
  }
  gemm_nn_kernel<<<dim3(4, 4, 8), 256>>>(na);
  bias1_kernel<<<4, 512>>>(in_proj_w, pre_b[0], pre_b[1], pre_b[2], pre_b[3]);
  tok_split_kernel<<<TOKN / 1024, 256>>>(tokens);

  /* 2. fused pre-proj(+perm) + in_proj (pipelined HMMA) */
  gemm_mma<0><<<dim3(4, 784), 256, SMEM_MM>>>(nullptr);

  /* 3. depthwise conv + silu */
  conv2_kernel<<<BTOT, 512>>>(conv_x_w, conv_x_b, conv_z_w, conv_z_b);

  /* 4. x_proj + layernorm */
  xdbl2_kernel<<<MROWS / 128, 256>>>(x_proj_w, ln_w, ln_b);

  /* 5. selective scan (fused dt_proj) */
  scan2_kernel<<<BTOT, 256>>>(A_log, dt_proj_b, D_param, dt_proj_w);

  /* 6. fused out_proj + gated post-projections (pipelined HMMA) */
  gemm_mma<1><<<dim3(4, 196), 256, SMEM_MM>>>(out);
}

// round 14
// speedup vs baseline: 2.4218x; 1.0526x over previous
#include <cuda_runtime.h>
#include <cuda_bf16.h>
#include <math.h>
#include <stdint.h>

#define DIMX 512
#define NPOS 49
#define BTOT 2048
#define DHALF 256
#define MROWS 100352    /* BTOT*NPOS */
#define GSTRIDE 25088   /* 512*49 */
#define TOKN 12845056   /* 512*49*512 */

/* ------------------- scratch (static, no allocation) ------------------- */
__device__ float g_xz   [(size_t)MROWS * DIMX];
__device__ float g_xconv[(size_t)MROWS * DHALF];
__device__ float g_dtin [(size_t)MROWS * 32];
__device__ float g_BC   [(size_t)MROWS * 16];
__device__ float g_bc   [4 * DIMX];
__device__ float g_b2   [DIMX];
__device__ float g_gates[4];
__device__ __nv_bfloat16 g_tok_h[TOKN];
__device__ __nv_bfloat16 g_tok_l[TOKN];
__device__ __nv_bfloat16 g_y_h[(size_t)MROWS * DIMX];
__device__ __nv_bfloat16 g_y_l[(size_t)MROWS * DIMX];
__device__ __nv_bfloat16 g_Wc_h[4 * DIMX * DIMX];
__device__ __nv_bfloat16 g_Wc_l[4 * DIMX * DIMX];
__device__ __nv_bfloat16 g_Wo_h[4 * DIMX * DIMX];
__device__ __nv_bfloat16 g_Wo_l[4 * DIMX * DIMX];

/* ------------------- permutation index tables ------------------- */
__constant__ int c_idx[4][49] = {
  { 0,1,2,3,4,5,6,7,8,9,10,11,12,13,14,15,16,17,18,19,20,21,22,23,24,
    25,26,27,28,29,30,31,32,33,34,35,36,37,38,39,40,41,42,43,44,45,46,47,48 },
  { 0,7,14,21,28,35,42, 1,8,15,22,29,36,43, 2,9,16,23,30,37,44,
    3,10,17,24,31,38,45, 4,11,18,25,32,39,46, 5,12,19,26,33,40,47,
    6,13,20,27,34,41,48 },
  { 0, 1,7, 2,8,14, 3,9,15,21, 4,10,16,22,28, 5,11,17,23,29,35,
    6,12,18,24,30,36,42, 13,19,25,31,37,43, 20,26,32,38,44,
    27,33,39,45, 34,40,46, 41,47, 48 },
  { 6, 5,13, 4,12,20, 3,11,19,27, 2,10,18,26,34, 1,9,17,25,33,41,
    0,8,16,24,32,40,48, 7,15,23,31,39,47, 14,22,30,38,46,
    21,29,37,45, 28,36,44, 35,43, 42 }
};

/* ======================= asm helpers ======================= */
__device__ __forceinline__ uint32_t smem_u32(const void* p) {
  uint32_t a;
  asm("{ .reg .u64 t; cvta.to.shared.u64 t, %1; cvt.u32.u64 %0, t; }" : "=r"(a) : "l"(p));
  return a;
}
__device__ __forceinline__ void ldsm4(uint32_t* r, uint32_t addr) {
  asm volatile("ldmatrix.sync.aligned.m8n8.x4.shared.b16 {%0,%1,%2,%3}, [%4];"
               : "=r"(r[0]), "=r"(r[1]), "=r"(r[2]), "=r"(r[3]) : "r"(addr));
}
__device__ __forceinline__ void mma16816(float* c, const uint32_t* a, const uint32_t* b) {
  asm volatile("mma.sync.aligned.m16n8k16.row.col.f32.bf16.bf16.f32 "
               "{%0,%1,%2,%3}, {%4,%5,%6,%7}, {%8,%9}, {%0,%1,%2,%3};"
               : "+f"(c[0]), "+f"(c[1]), "+f"(c[2]), "+f"(c[3])
               : "r"(a[0]), "r"(a[1]), "r"(a[2]), "r"(a[3]), "r"(b[0]), "r"(b[1]));
}
__device__ __forceinline__ void cpasync16(uint32_t dst, const void* src) {
  asm volatile("cp.async.cg.shared.global [%0], [%1], 16;" :: "r"(dst), "l"(src));
}
__device__ __forceinline__ void cpcommit() { asm volatile("cp.async.commit_group;" ::: "memory"); }
template<int N> __device__ __forceinline__ void cpwait() {
  asm volatile("cp.async.wait_group %0;" :: "n"(N) : "memory");
}

__device__ __forceinline__ void split4(float4 v, uint2& hi, uint2& lo) {
  __nv_bfloat162 h0 = __floats2bfloat162_rn(v.x, v.y);
  __nv_bfloat162 h1 = __floats2bfloat162_rn(v.z, v.w);
  float rx = v.x - __bfloat162float(h0.x);
  float ry = v.y - __bfloat162float(h0.y);
  float rz = v.z - __bfloat162float(h1.x);
  float rw = v.w - __bfloat162float(h1.y);
  __nv_bfloat162 l0 = __floats2bfloat162_rn(rx, ry);
  __nv_bfloat162 l1 = __floats2bfloat162_rn(rz, rw);
  hi.x = *(uint32_t*)&h0; hi.y = *(uint32_t*)&h1;
  lo.x = *(uint32_t*)&l0; lo.y = *(uint32_t*)&l1;
}

/* smem: 2 stages x (A 2 planes 128x144B, B 2 planes 256x144B) */
#define LDA      72
#define A_PLANE  18432
#define B_PLANE  36864
#define P_AH     0
#define P_AL     18432
#define P_BH     36864
#define P_BL     73728
#define STAGE_B  110592
#define OFF_AOFF 221184
#define SMEM_MM  221760

/* =================== cp.async-pipelined HMMA split-bf16 GEMM, 128x256 tile =================== */
template<int G2>
__global__ void __launch_bounds__(256) gemm_mma(float* __restrict__ dstp) {
  extern __shared__ __align__(16) char sm[];
  const int NCH = G2 ? 32 : 8;
  int tid = threadIdx.x, wid = tid >> 5, lane = tid & 31;
  int warp_m = wid & 1, warp_n = wid >> 1;          /* 2 x 4 warps, 64x64 each */
  int bm = blockIdx.y, bn = blockIdx.x;
  int m0 = bm * 128, n0 = bn * 256;
  uint32_t smb = smem_u32(sm);

  int* aoff = (int*)(sm + OFF_AOFF);
  int g1 = 0;
  if (!G2) {
    g1 = bm / 196;
    if (tid < 128) {
      int m = m0 + tid - g1 * GSTRIDE;
      int b = m / 49, i = m - b * 49;
      aoff[tid] = (b * 49 + c_idx[g1][i]) * DIMX;
    }
    __syncthreads();
  }

  const __nv_bfloat16* Wh_base = G2 ? g_Wo_h : g_Wc_h;
  const __nv_bfloat16* Wl_base = G2 ? g_Wo_l : g_Wc_l;

  auto prefetch = [&](int c) {
    int s = c & 1;
    int gq = G2 ? (c >> 3) : g1;
    int k0 = (G2 ? (c & 7) : c) * 64;
    uint32_t stg = smb + s * STAGE_B;
    const __nv_bfloat16* ah;
    const __nv_bfloat16* al;
    const __nv_bfloat16* wh = Wh_base + ((size_t)gq * DIMX + n0) * DIMX + k0;
    const __nv_bfloat16* wl = Wl_base + ((size_t)gq * DIMX + n0) * DIMX + k0;
    if (G2) {
      ah = g_y_h + (size_t)(gq * GSTRIDE + m0) * DIMX + k0;
      al = g_y_l + (size_t)(gq * GSTRIDE + m0) * DIMX + k0;
    } else {
      ah = g_tok_h + k0;
      al = g_tok_l + k0;
    }
#pragma unroll
    for (int i = 0; i < 4; ++i) {            /* A: 128 rows x 8 x 16B, 2 planes */
      int idx = tid + i * 256;
      int r = idx >> 3, j = idx & 7;
      uint32_t d = stg + r * 144 + j * 16;
      size_t arow = G2 ? (size_t)r * DIMX : (size_t)aoff[r];
      cpasync16(d + P_AH, ah + arow + j * 8);
      cpasync16(d + P_AL, al + arow + j * 8);
    }
#pragma unroll
    for (int i = 0; i < 8; ++i) {            /* B: 256 rows x 8 x 16B, 2 planes */
      int idx = tid + i * 256;
      int r = idx >> 3, j = idx & 7;
      uint32_t d = stg + P_BH + r * 144 + j * 16;
      const __nv_bfloat16* s1 = wh + (size_t)r * DIMX + j * 8;
      const __nv_bfloat16* s2 = wl + (size_t)r * DIMX + j * 8;
      cpasync16(d, s1);
      cpasync16(d + B_PLANE, s2);
    }
  };

  float acc[4][8][4];
#pragma unroll
  for (int t = 0; t < 4; ++t)
#pragma unroll
    for (int n = 0; n < 8; ++n)
#pragma unroll
      for (int e = 0; e < 4; ++e) acc[t][n][e] = 0.f;

  uint32_t a_row = warp_m * 64 + (lane & 15);
  uint32_t a_coff = (lane >> 4) << 3;
  uint32_t b_row = warp_n * 64 + ((lane >> 4) << 3) + (lane & 7);
  uint32_t b_coff = ((lane >> 3) & 1) << 3;

  prefetch(0); cpcommit();

  for (int c = 0; c < NCH; ++c) {
    if (c + 1 < NCH) { prefetch(c + 1); cpcommit(); cpwait<1>(); }
    else             { cpwait<0>(); }
    __syncthreads();
    uint32_t stg = smb + (c & 1) * STAGE_B;
#pragma unroll
    for (int kk = 0; kk < 4; ++kk) {
      int k = kk * 16;
      uint32_t ah[4][4], al[4][4], bh[8][2], bl[8][2];
#pragma unroll
      for (int t = 0; t < 4; ++t) {
        uint32_t off = ((a_row + t * 16) * LDA + k + a_coff) * 2;
        ldsm4(ah[t], stg + P_AH + off);
        ldsm4(al[t], stg + P_AL + off);
      }
#pragma unroll
      for (int p = 0; p < 4; ++p) {
        uint32_t off = ((b_row + p * 16) * LDA + k + b_coff) * 2;
        uint32_t rh[4], rl[4];
        ldsm4(rh, stg + P_BH + off);
        ldsm4(rl, stg + P_BL + off);
        bh[2*p][0] = rh[0]; bh[2*p][1] = rh[1]; bh[2*p+1][0] = rh[2]; bh[2*p+1][1] = rh[3];
        bl[2*p][0] = rl[0]; bl[2*p][1] = rl[1]; bl[2*p+1][0] = rl[2]; bl[2*p+1][1] = rl[3];
      }
#pragma unroll
      for (int t = 0; t < 4; ++t)
#pragma unroll
        for (int n = 0; n < 8; ++n) {
          mma16816(acc[t][n], ah[t], bh[n]);
          mma16816(acc[t][n], al[t], bh[n]);
          mma16816(acc[t][n], ah[t], bl[n]);
        }
    }
    __syncthreads();
  }

  const float* bias = (G2 ? g_b2 : g_bc + g1 * DIMX) + n0;
  float* dst = G2 ? dstp : g_xz;
#pragma unroll
  for (int t = 0; t < 4; ++t) {
    int mrow = m0 + warp_m * 64 + t * 16 + (lane >> 2);
#pragma unroll
    for (int n = 0; n < 8; ++n) {
      int cl = warp_n * 64 + n * 8 + (lane & 3) * 2;
      float b0 = bias[cl], b1 = bias[cl + 1];
      float2 v0 = {acc[t][n][0] + b0, acc[t][n][1] + b1};
      float2 v1 = {acc[t][n][2] + b0, acc[t][n][3] + b1};
      *(float2*)(dst + (size_t)mrow * DIMX + n0 + cl) = v0;
      *(float2*)(dst + (size_t)(mrow + 8) * DIMX + n0 + cl) = v1;
    }
  }
}

/* ------------------- fp32 prep GEMM -> bf16 planes ------------------- */
__device__ __forceinline__ void tile_fma(const float (&As)[8][128], const float (&Ws)[8][128],
                                         float (&acc)[8][8], int tm, int tn) {
#pragma unroll
  for (int k = 0; k < 8; ++k) {
    float4 a0 = *(const float4*)&As[k][tm];
    float4 a1 = *(const float4*)&As[k][tm + 4];
    float4 w0 = *(const float4*)&Ws[k][tn];
    float4 w1 = *(const float4*)&Ws[k][tn + 4];
    float a[8] = {a0.x,a0.y,a0.z,a0.w,a1.x,a1.y,a1.z,a1.w};
    float w[8] = {w0.x,w0.y,w0.z,w0.w,w1.x,w1.y,w1.z,w1.w};
#pragma unroll
    for (int i = 0; i < 8; ++i)
#pragma unroll
      for (int j = 0; j < 8; ++j)
        acc[i][j] = fmaf(a[i], w[j], acc[i][j]);
  }
}

struct NNArgs { const float* A[8]; const float* B[8]; };

__global__ void __launch_bounds__(256) gemm_nn_kernel(NNArgs args) {
  __shared__ __align__(16) float As[8][128];
  __shared__ __align__(16) float Bs[8][128];
  int tid = threadIdx.x;
  int z = blockIdx.z;
  const float* __restrict__ A = args.A[z];
  const float* __restrict__ B = args.B[z];
  __nv_bfloat16* Ch = (z < 4) ? (g_Wc_h + (size_t)z * DIMX * DIMX)
                              : (g_Wo_h + (size_t)(z - 4) * DIMX * DIMX);
  __nv_bfloat16* Cl = (z < 4) ? (g_Wc_l + (size_t)z * DIMX * DIMX)
                              : (g_Wo_l + (size_t)(z - 4) * DIMX * DIMX);
  float gate = (z < 4) ? 1.f : g_gates[z - 4];
  int m0 = blockIdx.x * 128, n0 = blockIdx.y * 128;
  float acc[8][8];
#pragma unroll
  for (int i = 0; i < 8; ++i)
#pragma unroll
    for (int j = 0; j < 8; ++j) acc[i][j] = 0.f;
  int ar = tid >> 1, ac = (tid & 1) * 4;
  int bk = tid >> 5, bn = (tid & 31) * 4;
  for (int k0 = 0; k0 < DIMX; k0 += 8) {
    float4 av = *(const float4*)(A + (size_t)(m0 + ar) * DIMX + k0 + ac);
    float4 bv = *(const float4*)(B + (size_t)(k0 + bk) * DIMX + n0 + bn);
    As[ac][ar] = av.x; As[ac+1][ar] = av.y; As[ac+2][ar] = av.z; As[ac+3][ar] = av.w;
    *(float4*)&Bs[bk][bn] = bv;
    __syncthreads();
    tile_fma(As, Bs, acc, (tid >> 4) * 8, (tid & 15) * 8);
    __syncthreads();
  }
  int tm = (tid >> 4) * 8, tn = (tid & 15) * 8;
#pragma unroll
  for (int i = 0; i < 8; ++i) {
    size_t base = (size_t)(m0 + tm + i) * DIMX + n0 + tn;
#pragma unroll
    for (int j = 0; j < 8; j += 4) {
      float4 v = {acc[i][j] * gate, acc[i][j+1] * gate, acc[i][j+2] * gate, acc[i][j+3] * gate};
      uint2 hi, lo;
      split4(v, hi, lo);
      *(uint2*)(Ch + base + j) = hi;
      *(uint2*)(Cl + base + j) = lo;
    }
  }
}

/* ---------- tokens -> bf16 hi/lo planes ---------- */
__global__ void __launch_bounds__(256) tok_split_kernel(const float* __restrict__ tokens) {
  size_t i4 = ((size_t)blockIdx.x * blockDim.x + threadIdx.x) * 4;
  float4 v = *(const float4*)(tokens + i4);
  uint2 hi, lo;
  split4(v, hi, lo);
  *(uint2*)(g_tok_h + i4) = hi;
  *(uint2*)(g_tok_l + i4) = lo;
}

/* ---------- merged small prep: blocks 0-3 = bias1, block 4 = gates + b2 ---------- */
__global__ void __launch_bounds__(512) prep_small_kernel(
    const float* __restrict__ inW,
    const float* pb0, const float* pb1, const float* pb2, const float* pb3,
    const float* __restrict__ gl,
    const float* qb0, const float* qb1, const float* qb2, const float* qb3) {
  int t = threadIdx.x;
  if (blockIdx.x < 4) {
    int g = blockIdx.x;
    const float* pb = (g == 0) ? pb0 : (g == 1) ? pb1 : (g == 2) ? pb2 : pb3;
    const float* wr = inW + (size_t)t * DIMX;
    float s = 0.f;
    for (int k = 0; k < DIMX; ++k) s = fmaf(wr[k], pb[k], s);
    g_bc[g * DIMX + t] = s;
  } else {
    __shared__ float sg[4];
    if (t == 0) {
      float a0 = gl[0], a1 = gl[1], a2 = gl[2], a3 = gl[3];
      float m = fmaxf(fmaxf(a0, a1), fmaxf(a2, a3));
      float e0 = __expf(a0 - m), e1 = __expf(a1 - m), e2 = __expf(a2 - m), e3 = __expf(a3 - m);
      float inv = 1.f / (e0 + e1 + e2 + e3);
      sg[0] = e0 * inv; sg[1] = e1 * inv; sg[2] = e2 * inv; sg[3] = e3 * inv;
      g_gates[0] = sg[0]; g_gates[1] = sg[1]; g_gates[2] = sg[2]; g_gates[3] = sg[3];
    }
    __syncthreads();
    g_b2[t] = sg[0]*qb0[t] + sg[1]*qb1[t] + sg[2]*qb2[t] + sg[3]*qb3[t];
  }
}

/* ---------- depthwise conv(k=3) + silu ---------- */
__global__ void __launch_bounds__(512) conv2_kernel(const float* __restrict__ cxw,
                                                    const float* __restrict__ cxb,
                                                    const float* __restrict__ czw,
                                                    const float* __restrict__ czb) {
  int b = blockIdx.x, t = threadIdx.x;
  int d = t & 255;
  bool isz = t >= 256;
  float w0 = isz ? czw[d*3]   : cxw[d*3];
  float w1 = isz ? czw[d*3+1] : cxw[d*3+1];
  float w2 = isz ? czw[d*3+2] : cxw[d*3+2];
  float bb = isz ? czb[d]     : cxb[d];
  const float* base = g_xz + (size_t)b * 49 * DIMX + (isz ? DHALF : 0) + d;
  float* outx = g_xconv + (size_t)b * 49 * DHALF + d;
  size_t zoff = (size_t)b * 49 * DIMX + DHALF + d;
  float prev = 0.f, cur = base[0], next;
  for (int l = 0; l < 49; ++l) {
    next = (l < 48) ? base[(size_t)(l + 1) * DIMX] : 0.f;
    float v = fmaf(w0, prev, fmaf(w1, cur, fmaf(w2, next, bb)));
    v = v / (1.f + __expf(-v));
    if (isz) {
      __nv_bfloat16 h = __float2bfloat16(v);
      g_y_h[zoff + (size_t)l * DIMX] = h;
      g_y_l[zoff + (size_t)l * DIMX] = __float2bfloat16(v - __bfloat162float(h));
    } else {
      outx[(size_t)l * DHALF] = v;
    }
    prev = cur; cur = next;
  }
}

/* ---------- x_proj GEMM (128x48, K=256) + layernorm(48) fused ---------- */
__global__ void __launch_bounds__(256) xdbl2_kernel(const float* __restrict__ xpw,
                                                    const float* __restrict__ lnw,
                                                    const float* __restrict__ lnb) {
  __shared__ __align__(16) float As[16][132];
  __shared__ __align__(16) float Ws[16][52];
  __shared__ float xd[128][49];
  int tid = threadIdx.x;
  int m0 = blockIdx.x * 128;
  int tm = (tid >> 3) * 4;
  int tn = (tid & 7) * 6;
  float acc[4][6];
#pragma unroll
  for (int i = 0; i < 4; ++i)
#pragma unroll
    for (int j = 0; j < 6; ++j) acc[i][j] = 0.f;

  for (int k0 = 0; k0 < DHALF; k0 += 16) {
#pragma unroll
    for (int i = 0; i < 2; ++i) {
      int fid = tid + i * 256;
      int r = fid >> 2, c4 = fid & 3;
      float4 v = *(const float4*)(g_xconv + (size_t)(m0 + r) * DHALF + k0 + c4 * 4);
      As[c4*4+0][r] = v.x; As[c4*4+1][r] = v.y; As[c4*4+2][r] = v.z; As[c4*4+3][r] = v.w;
    }
    if (tid < 192) {
      int e = tid >> 2, c4 = tid & 3;
      float4 v = *(const float4*)(xpw + (size_t)e * DHALF + k0 + c4 * 4);
      Ws[c4*4+0][e] = v.x; Ws[c4*4+1][e] = v.y; Ws[c4*4+2][e] = v.z; Ws[c4*4+3][e] = v.w;
    }
    __syncthreads();
#pragma unroll
    for (int k = 0; k < 16; ++k) {
      float4 a4 = *(const float4*)&As[k][tm];
      float a[4] = {a4.x, a4.y, a4.z, a4.w};
      float w[6];
#pragma unroll
      for (int j = 0; j < 6; ++j) w[j] = Ws[k][tn + j];
#pragma unroll
      for (int i = 0; i < 4; ++i)
#pragma unroll
        for (int j = 0; j < 6; ++j) acc[i][j] = fmaf(a[i], w[j], acc[i][j]);
    }
    __syncthreads();
  }
#pragma unroll
  for (int i = 0; i < 4; ++i)
#pragma unroll
    for (int j = 0; j < 6; ++j) xd[tm + i][tn + j] = acc[i][j];
  __syncthreads();

  if (tid < 128) {
    float s = 0.f, sq = 0.f;
#pragma unroll
    for (int e = 0; e < 48; ++e) { float v = xd[tid][e]; s += v; sq += v * v; }
    float mean = s * (1.f / 48.f);
    float var = sq * (1.f / 48.f) - mean * mean;
    float rstd = rsqrtf(var + 1e-5f);
    size_t grow = m0 + tid;
    float* dtp = g_dtin + grow * 32;
    float* bcp = g_BC + grow * 16;
#pragma unroll
    for (int e = 0; e < 32; ++e)
      dtp[e] = (xd[tid][e] - mean) * rstd * lnw[e] + lnb[e];
#pragma unroll
    for (int e = 0; e < 16; ++e)
      bcp[e] = (xd[tid][32 + e] - mean) * rstd * lnw[32 + e] + lnb[32 + e];
  }
}

/* ---------- selective scan w/ fused dt_proj; y -> bf16 planes ---------- */
__global__ void __launch_bounds__(256) scan2_kernel(const float* __restrict__ A_log,
                                                    const float* __restrict__ dtb_v,
                                                    const float* __restrict__ Dp,
                                                    const float* __restrict__ dtw) {
  __shared__ float bc[49 * 16];
  __shared__ float sdt[49 * 32];
  int b = blockIdx.x, d = threadIdx.x;
  for (int i = d; i < 49 * 16; i += 256) bc[i] = g_BC[(size_t)b * 49 * 16 + i];
  for (int i = d; i < 49 * 32; i += 256) sdt[i] = g_dtin[(size_t)b * 49 * 32 + i];
  __syncthreads();
  float wv[32];
#pragma unroll
  for (int j = 0; j < 8; ++j) {
    float4 v = *(const float4*)(dtw + (size_t)d * 32 + j * 4);
    wv[j*4] = v.x; wv[j*4+1] = v.y; wv[j*4+2] = v.z; wv[j*4+3] = v.w;
  }
  float Ar[8];
#pragma unroll
  for (int n = 0; n < 8; ++n) Ar[n] = -expf(A_log[d * 8 + n]);
  float dtb = dtb_v[d], Dv = Dp[d];
  float h[8];
#pragma unroll
  for (int n = 0; n < 8; ++n) h[n] = 0.f;
  const float* up = g_xconv + (size_t)b * 49 * DHALF + d;
  size_t yoff = (size_t)b * 49 * DIMX + d;
  for (int l = 0; l < 49; ++l) {
    const float* dl = &sdt[l * 32];
    float dtv = dtb;
#pragma unroll
    for (int k = 0; k < 32; ++k) dtv = fmaf(wv[k], dl[k], dtv);
    dtv = (dtv > 20.f) ? dtv : log1pf(__expf(dtv));
    float u = up[l * DHALF];
    float dbu = dtv * u;
    const float* B = &bc[l * 16];
    float y = 0.f;
#pragma unroll
    for (int n = 0; n < 8; ++n) {
      h[n] = fmaf(h[n], __expf(dtv * Ar[n]), dbu * B[n]);
      y = fmaf(h[n], B[8 + n], y);
    }
    y = fmaf(Dv, u, y);
    if (!isfinite(y)) y = isnan(y) ? 0.f : copysignf(3.402823466e38f, y);
    __nv_bfloat16 hh = __float2bfloat16(y);
    g_y_h[yoff + (size_t)l * DIMX] = hh;
    g_y_l[yoff + (size_t)l * DIMX] = __float2bfloat16(y - __bfloat162float(hh));
  }
}

/* ------------------- launch ------------------- */
extern "C" void kernel_launch(void* const* d_in, const int* in_sizes, int n_in,
                              void* d_out, int out_size) {
  const float *tokens, *pre_w[4], *pre_b[4], *post_w[4], *post_b[4];
  const float *in_proj_w, *conv_x_w, *conv_x_b, *conv_z_w, *conv_z_b;
  const float *x_proj_w, *ln_w, *ln_b, *dt_proj_w, *dt_proj_b;
  const float *A_log, *D_param, *out_proj_w, *gate_logits;

  tokens = (const float*)d_in[0];
  for (int g = 0; g < 4; ++g) {
    pre_w[g] = (const float*)d_in[1 + 2 * g];
    pre_b[g] = (const float*)d_in[2 + 2 * g];
  }
  if (in_sizes[10] == 768) {
    in_proj_w = (const float*)d_in[9];
    conv_x_w = (const float*)d_in[10]; conv_x_b = (const float*)d_in[11];
    conv_z_w = (const float*)d_in[12]; conv_z_b = (const float*)d_in[13];
    x_proj_w = (const float*)d_in[14];
    ln_w = (const float*)d_in[15]; ln_b = (const float*)d_in[16];
    dt_proj_w = (const float*)d_in[17]; dt_proj_b = (const float*)d_in[18];
    A_log = (const float*)d_in[19]; D_param = (const float*)d_in[20];
    out_proj_w = (const float*)d_in[21];
    for (int g = 0; g < 4; ++g) {
      post_w[g] = (const float*)d_in[22 + 2 * g];
      post_b[g] = (const float*)d_in[23 + 2 * g];
    }
    gate_logits = (const float*)d_in[30];
  } else {
    for (int g = 0; g < 4; ++g) {
      post_w[g] = (const float*)d_in[9 + 2 * g];
      post_b[g] = (const float*)d_in[10 + 2 * g];
    }
    in_proj_w = (const float*)d_in[17];
    conv_x_w = (const float*)d_in[18]; conv_x_b = (const float*)d_in[19];
    conv_z_w = (const float*)d_in[20]; conv_z_b = (const float*)d_in[21];
    x_proj_w = (const float*)d_in[22];
    ln_w = (const float*)d_in[23]; ln_b = (const float*)d_in[24];
    dt_proj_w = (const float*)d_in[25]; dt_proj_b = (const float*)d_in[26];
    A_log = (const float*)d_in[27]; D_param = (const float*)d_in[28];
    out_proj_w = (const float*)d_in[29];
    gate_logits = (const float*)d_in[30];
  }
  float* out = (float*)d_out;

  cudaFuncSetAttribute(gemm_mma<0>, cudaFuncAttributeMaxDynamicSharedMemorySize, SMEM_MM);
  cudaFuncSetAttribute(gemm_mma<1>, cudaFuncAttributeMaxDynamicSharedMemorySize, SMEM_MM);

  /* 1. prep: gates+b2+bias1 merged (launch #1) */
  prep_small_kernel<<<5, 512>>>(in_proj_w, pre_b[0], pre_b[1], pre_b[2], pre_b[3],
                                gate_logits, post_b[0], post_b[1], post_b[2], post_b[3]);
  /* 2. weight folding -> bf16 planes (launch #2) */
  NNArgs na;
  for (int g = 0; g < 4; ++g) {
    na.A[g] = in_proj_w;  na.B[g] = pre_w[g];
    na.A[4+g] = post_w[g]; na.B[4+g] = out_proj_w;
  }
  gemm_nn_kernel<<<dim3(4, 4, 8), 256>>>(na);
  /* 3. token planes (launch #3) */
  tok_split_kernel<<<TOKN / 1024, 256>>>(tokens);

  /* 4. fused pre-proj(+perm) + in_proj — PROFILED SLOT (launch #4) */
  gemm_mma<0><<<dim3(2, 784), 256, SMEM_MM>>>(nullptr);

  /* 5-7. conv, x_proj+LN, scan */
  conv2_kernel<<<BTOT, 512>>>(conv_x_w, conv_x_b, conv_z_w, conv_z_b);
  xdbl2_kernel<<<MROWS / 128, 256>>>(x_proj_w, ln_w, ln_b);
  scan2_kernel<<<BTOT, 256>>>(A_log, dt_proj_b, D_param, dt_proj_w);

  /* 8. fused out_proj + gated post-projections */
  gemm_mma<1><<<dim3(2, 196), 256, SMEM_MM>>>(out);
}